// round 8
// baseline (speedup 1.0000x reference)
#include <cuda_runtime.h>
#include <math_constants.h>

#define B   8
#define T   1024
#define KD  256
#define H   8
#define MM  (B*T)     // 8192
#define NN  (H*KD)    // 2048

// Scratch (device globals — no allocation allowed)
__device__ float g_Q[B*H*T*KD];   // [b,h,t,d]
__device__ float g_K[B*H*T*KD];
__device__ float g_V[B*H*T*KD];
__device__ float g_O[B*T*H*KD];   // [b,t,h*d]

// ---------------------------------------------------------------------------
// QKV projection: C = X @ W, written to [b,h,t,d], scaled by 0.25 for Q and K.
// 128x128 tile, BK=8, 256 threads, 8x8 register tile.
// ---------------------------------------------------------------------------
__global__ __launch_bounds__(256) void qkv_gemm(
    const float* __restrict__ X,
    const float* __restrict__ Wq,
    const float* __restrict__ Wk,
    const float* __restrict__ Wv)
{
    __shared__ float As[8][128];
    __shared__ float Bs[8][128];

    const int which = blockIdx.z;
    const float* W = (which == 0) ? Wq : (which == 1) ? Wk : Wv;
    float* Out     = (which == 0) ? g_Q : (which == 1) ? g_K : g_V;
    const float scale = (which == 2) ? 1.0f : 0.25f;   // 256^(1/4) = 4

    const int bm = blockIdx.y * 128;
    const int bn = blockIdx.x * 128;
    const int tid  = threadIdx.x;
    const int arow = tid >> 1,  acol = (tid & 1) * 4;
    const int brow = tid >> 5,  bcol = (tid & 31) * 4;
    const int tx = tid & 15,    ty = tid >> 4;

    float acc[8][8];
#pragma unroll
    for (int i = 0; i < 8; i++)
#pragma unroll
        for (int j = 0; j < 8; j++) acc[i][j] = 0.f;

    for (int k0 = 0; k0 < KD; k0 += 8) {
        float4 a4 = *(const float4*)(X + (size_t)(bm + arow) * KD + k0 + acol);
        float4 b4 = *(const float4*)(W + (size_t)(k0 + brow) * NN + bn + bcol);
        As[acol + 0][arow] = a4.x; As[acol + 1][arow] = a4.y;
        As[acol + 2][arow] = a4.z; As[acol + 3][arow] = a4.w;
        *(float4*)&Bs[brow][bcol] = b4;
        __syncthreads();
#pragma unroll
        for (int kk = 0; kk < 8; kk++) {
            float4 a0 = *(float4*)&As[kk][ty * 4];
            float4 a1 = *(float4*)&As[kk][64 + ty * 4];
            float4 b0 = *(float4*)&Bs[kk][tx * 4];
            float4 b1 = *(float4*)&Bs[kk][64 + tx * 4];
            float a[8] = {a0.x, a0.y, a0.z, a0.w, a1.x, a1.y, a1.z, a1.w};
            float b[8] = {b0.x, b0.y, b0.z, b0.w, b1.x, b1.y, b1.z, b1.w};
#pragma unroll
            for (int i = 0; i < 8; i++)
#pragma unroll
                for (int j = 0; j < 8; j++)
                    acc[i][j] = fmaf(a[i], b[j], acc[i][j]);
        }
        __syncthreads();
    }

#pragma unroll
    for (int i = 0; i < 8; i++) {
        int m = bm + ((i < 4) ? (ty * 4 + i) : (64 + ty * 4 + (i - 4)));
        int bb = m >> 10, tt = m & (T - 1);
#pragma unroll
        for (int jj = 0; jj < 2; jj++) {
            int n0 = bn + ((jj == 0) ? (tx * 4) : (64 + tx * 4));
            int hh = n0 >> 8, dd = n0 & (KD - 1);
            float4 o;
            o.x = acc[i][jj * 4 + 0] * scale;
            o.y = acc[i][jj * 4 + 1] * scale;
            o.z = acc[i][jj * 4 + 2] * scale;
            o.w = acc[i][jj * 4 + 3] * scale;
            *(float4*)(Out + ((((size_t)bb * H + hh) * T + tt) * KD + dd)) = o;
        }
    }
}

// ---------------------------------------------------------------------------
// Flash attention: one CTA = one (b,h) x 64-query tile, loops over 16 key
// tiles of 64. Q/K/V tiles (64x256 fp32 each) + P tile (64x64) in SMEM.
// K tile stores each float4 group g of row n at g ^ ((n>>2)&7) so the
// tx-strided QK^T reads are bank-conflict-free.
// ---------------------------------------------------------------------------
#define BR 64
#define BC 64

__global__ __launch_bounds__(256, 1) void attn_kernel()
{
    extern __shared__ float sm[];
    float* Qs = sm;                       // 64*256
    float* Ks = sm + BR * KD;             // 64*256 (swizzled)
    float* Vs = sm + 2 * BR * KD;         // 64*256
    float* Ps = sm + 3 * BR * KD;         // 64*64

    const int tid = threadIdx.x;
    const int tx = tid & 15, ty = tid >> 4;
    const int bh = blockIdx.y;
    const int q0 = blockIdx.x * BR;

    const float* Qg = g_Q + (size_t)bh * T * KD + (size_t)q0 * KD;
    const float* Kg = g_K + (size_t)bh * T * KD;
    const float* Vg = g_V + (size_t)bh * T * KD;

    // Load Q tile (natural layout, coalesced)
    for (int i = tid; i < BR * KD / 4; i += 256) {
        int r = i >> 6, g = i & 63;
        *(float4*)&Qs[r * KD + g * 4] = *(const float4*)(Qg + (size_t)r * KD + g * 4);
    }

    float m_i[4], l_i[4], o_acc[4][16];
#pragma unroll
    for (int i = 0; i < 4; i++) {
        m_i[i] = -CUDART_INF_F; l_i[i] = 0.f;
#pragma unroll
        for (int q = 0; q < 16; q++) o_acc[i][q] = 0.f;
    }
    __syncthreads();

    const int swz = tx & 7;

    for (int kt = 0; kt < T / BC; kt++) {
        const float* Kt = Kg + (size_t)kt * BC * KD;
        const float* Vt = Vg + (size_t)kt * BC * KD;
        // Load K (swizzled groups) and V (natural)
        for (int i = tid; i < BC * KD / 4; i += 256) {
            int n = i >> 6, g = i & 63;
            int pg = g ^ ((n >> 2) & 7);
            *(float4*)&Ks[n * KD + pg * 4] = *(const float4*)(Kt + (size_t)n * KD + g * 4);
            *(float4*)&Vs[n * KD + g * 4]  = *(const float4*)(Vt + (size_t)n * KD + g * 4);
        }
        __syncthreads();

        // S tile: rows ty*4+i, cols tx*4+j, contraction over 256 dims
        float s[4][4];
#pragma unroll
        for (int i = 0; i < 4; i++)
#pragma unroll
            for (int j = 0; j < 4; j++) s[i][j] = 0.f;

#pragma unroll 4
        for (int g = 0; g < 64; g++) {
            float4 a[4], bb4[4];
#pragma unroll
            for (int i = 0; i < 4; i++)
                a[i] = *(float4*)&Qs[(ty * 4 + i) * KD + g * 4];
            int pg4 = (g ^ swz) * 4;
#pragma unroll
            for (int j = 0; j < 4; j++)
                bb4[j] = *(float4*)&Ks[(tx * 4 + j) * KD + pg4];
#pragma unroll
            for (int i = 0; i < 4; i++)
#pragma unroll
                for (int j = 0; j < 4; j++) {
                    s[i][j] = fmaf(a[i].x, bb4[j].x, s[i][j]);
                    s[i][j] = fmaf(a[i].y, bb4[j].y, s[i][j]);
                    s[i][j] = fmaf(a[i].z, bb4[j].z, s[i][j]);
                    s[i][j] = fmaf(a[i].w, bb4[j].w, s[i][j]);
                }
        }

        // Online softmax (row groups are aligned 16-lane half-warps)
#pragma unroll
        for (int i = 0; i < 4; i++) {
            float mx = fmaxf(fmaxf(s[i][0], s[i][1]), fmaxf(s[i][2], s[i][3]));
            mx = fmaxf(mx, __shfl_xor_sync(0xffffffffu, mx, 1));
            mx = fmaxf(mx, __shfl_xor_sync(0xffffffffu, mx, 2));
            mx = fmaxf(mx, __shfl_xor_sync(0xffffffffu, mx, 4));
            mx = fmaxf(mx, __shfl_xor_sync(0xffffffffu, mx, 8));
            float m_new = fmaxf(m_i[i], mx);
            float corr  = __expf(m_i[i] - m_new);
            float rsum = 0.f;
#pragma unroll
            for (int j = 0; j < 4; j++) {
                s[i][j] = __expf(s[i][j] - m_new);
                rsum += s[i][j];
            }
            rsum += __shfl_xor_sync(0xffffffffu, rsum, 1);
            rsum += __shfl_xor_sync(0xffffffffu, rsum, 2);
            rsum += __shfl_xor_sync(0xffffffffu, rsum, 4);
            rsum += __shfl_xor_sync(0xffffffffu, rsum, 8);
            l_i[i] = l_i[i] * corr + rsum;
            m_i[i] = m_new;
#pragma unroll
            for (int q = 0; q < 16; q++) o_acc[i][q] *= corr;
        }

        // Publish P tile
#pragma unroll
        for (int i = 0; i < 4; i++) {
            float4 pv = make_float4(s[i][0], s[i][1], s[i][2], s[i][3]);
            *(float4*)&Ps[(ty * 4 + i) * 64 + tx * 4] = pv;
        }
        __syncthreads();

        // O += P @ V : rows ty*4+i, d-cols (tx + 16q)*4
#pragma unroll 2
        for (int c = 0; c < BC; c++) {
            float p[4];
#pragma unroll
            for (int i = 0; i < 4; i++) p[i] = Ps[(ty * 4 + i) * 64 + c];
#pragma unroll
            for (int q = 0; q < 4; q++) {
                float4 v = *(float4*)&Vs[c * KD + (tx + 16 * q) * 4];
#pragma unroll
                for (int i = 0; i < 4; i++) {
                    o_acc[i][q * 4 + 0] = fmaf(p[i], v.x, o_acc[i][q * 4 + 0]);
                    o_acc[i][q * 4 + 1] = fmaf(p[i], v.y, o_acc[i][q * 4 + 1]);
                    o_acc[i][q * 4 + 2] = fmaf(p[i], v.z, o_acc[i][q * 4 + 2]);
                    o_acc[i][q * 4 + 3] = fmaf(p[i], v.w, o_acc[i][q * 4 + 3]);
                }
            }
        }
        __syncthreads();
    }

    // Finalize and write to g_O [b, t, h*KD]
    const int bb = bh >> 3, hh = bh & 7;
#pragma unroll
    for (int i = 0; i < 4; i++) {
        float inv = 1.0f / l_i[i];
        int tt = q0 + ty * 4 + i;
        float* Og = g_O + ((size_t)bb * T + tt) * NN + hh * KD;
#pragma unroll
        for (int q = 0; q < 4; q++) {
            float4 o;
            o.x = o_acc[i][q * 4 + 0] * inv;
            o.y = o_acc[i][q * 4 + 1] * inv;
            o.z = o_acc[i][q * 4 + 2] * inv;
            o.w = o_acc[i][q * 4 + 3] * inv;
            *(float4*)(Og + (tx + 16 * q) * 4) = o;
        }
    }
}

// ---------------------------------------------------------------------------
// Output projection: out = g_O[8192,2048] @ Wu[2048,256] + bu
// ---------------------------------------------------------------------------
__global__ __launch_bounds__(256) void out_gemm(
    const float* __restrict__ Wu,
    const float* __restrict__ bu,
    float* __restrict__ C)
{
    __shared__ float As[8][128];
    __shared__ float Bs[8][128];

    const int bm = blockIdx.y * 128;
    const int bn = blockIdx.x * 128;
    const int tid  = threadIdx.x;
    const int arow = tid >> 1,  acol = (tid & 1) * 4;
    const int brow = tid >> 5,  bcol = (tid & 31) * 4;
    const int tx = tid & 15,    ty = tid >> 4;

    float acc[8][8];
#pragma unroll
    for (int i = 0; i < 8; i++)
#pragma unroll
        for (int j = 0; j < 8; j++) acc[i][j] = 0.f;

    for (int k0 = 0; k0 < NN; k0 += 8) {
        float4 a4 = *(const float4*)(g_O + (size_t)(bm + arow) * NN + k0 + acol);
        float4 b4 = *(const float4*)(Wu + (size_t)(k0 + brow) * KD + bn + bcol);
        As[acol + 0][arow] = a4.x; As[acol + 1][arow] = a4.y;
        As[acol + 2][arow] = a4.z; As[acol + 3][arow] = a4.w;
        *(float4*)&Bs[brow][bcol] = b4;
        __syncthreads();
#pragma unroll
        for (int kk = 0; kk < 8; kk++) {
            float4 a0 = *(float4*)&As[kk][ty * 4];
            float4 a1 = *(float4*)&As[kk][64 + ty * 4];
            float4 b0 = *(float4*)&Bs[kk][tx * 4];
            float4 b1 = *(float4*)&Bs[kk][64 + tx * 4];
            float a[8] = {a0.x, a0.y, a0.z, a0.w, a1.x, a1.y, a1.z, a1.w};
            float b[8] = {b0.x, b0.y, b0.z, b0.w, b1.x, b1.y, b1.z, b1.w};
#pragma unroll
            for (int i = 0; i < 8; i++)
#pragma unroll
                for (int j = 0; j < 8; j++)
                    acc[i][j] = fmaf(a[i], b[j], acc[i][j]);
        }
        __syncthreads();
    }

#pragma unroll
    for (int i = 0; i < 8; i++) {
        int m = bm + ((i < 4) ? (ty * 4 + i) : (64 + ty * 4 + (i - 4)));
#pragma unroll
        for (int jj = 0; jj < 2; jj++) {
            int n0 = bn + ((jj == 0) ? (tx * 4) : (64 + tx * 4));
            float4 bias = *(const float4*)(bu + n0);
            float4 o;
            o.x = acc[i][jj * 4 + 0] + bias.x;
            o.y = acc[i][jj * 4 + 1] + bias.y;
            o.z = acc[i][jj * 4 + 2] + bias.z;
            o.w = acc[i][jj * 4 + 3] + bias.w;
            *(float4*)(C + (size_t)m * KD + n0) = o;
        }
    }
}

// ---------------------------------------------------------------------------

extern "C" void kernel_launch(void* const* d_in, const int* in_sizes, int n_in,
                              void* d_out, int out_size)
{
    const float* x  = (const float*)d_in[0];
    const float* Wq = (const float*)d_in[1];
    const float* Wk = (const float*)d_in[2];
    const float* Wv = (const float*)d_in[3];
    const float* Wu = (const float*)d_in[4];
    const float* bu = (const float*)d_in[5];
    float* out = (float*)d_out;

    const int ATTN_SMEM = (3 * BR * KD + BR * BC) * (int)sizeof(float); // 212992 B
    cudaFuncSetAttribute(attn_kernel, cudaFuncAttributeMaxDynamicSharedMemorySize,
                         ATTN_SMEM);

    // 1) QKV projections (grid.z: 0=Q, 1=K, 2=V)
    dim3 g1(NN / 128, MM / 128, 3);
    qkv_gemm<<<g1, 256>>>(x, Wq, Wk, Wv);

    // 2) Flash attention: (q-tiles, b*h)
    dim3 g2(T / BR, B * H);
    attn_kernel<<<g2, 256, ATTN_SMEM>>>();

    // 3) Output projection + bias
    dim3 g3(KD / 128, MM / 128);
    out_gemm<<<g3, 256>>>(Wu, bu, out);
}

// round 9
// speedup vs baseline: 1.0031x; 1.0031x over previous
#include <cuda_runtime.h>
#include <math_constants.h>

#define B   8
#define T   1024
#define KD  256
#define H   8
#define MM  (B*T)     // 8192
#define NN  (H*KD)    // 2048

// Scratch (device globals — no allocation allowed)
__device__ float g_Q[B*H*T*KD];   // [b,h,t,d]
__device__ float g_K[B*H*T*KD];
__device__ float g_V[B*H*T*KD];
__device__ float g_O[B*T*H*KD];   // [b,t,h*d]

// ---------------------------------------------------------------------------
// QKV projection: C = X @ W, written to [b,h,t,d], scaled by 0.25 for Q and K.
// 128x128 tile, BK=8, 256 threads, 8x8 register tile.
// ---------------------------------------------------------------------------
__global__ __launch_bounds__(256) void qkv_gemm(
    const float* __restrict__ X,
    const float* __restrict__ Wq,
    const float* __restrict__ Wk,
    const float* __restrict__ Wv)
{
    __shared__ float As[8][128];
    __shared__ float Bs[8][128];

    const int which = blockIdx.z;
    const float* W = (which == 0) ? Wq : (which == 1) ? Wk : Wv;
    float* Out     = (which == 0) ? g_Q : (which == 1) ? g_K : g_V;
    const float scale = (which == 2) ? 1.0f : 0.25f;   // 256^(1/4) = 4

    const int bm = blockIdx.y * 128;
    const int bn = blockIdx.x * 128;
    const int tid  = threadIdx.x;
    const int arow = tid >> 1,  acol = (tid & 1) * 4;
    const int brow = tid >> 5,  bcol = (tid & 31) * 4;
    const int tx = tid & 15,    ty = tid >> 4;

    float acc[8][8];
#pragma unroll
    for (int i = 0; i < 8; i++)
#pragma unroll
        for (int j = 0; j < 8; j++) acc[i][j] = 0.f;

    for (int k0 = 0; k0 < KD; k0 += 8) {
        float4 a4 = *(const float4*)(X + (size_t)(bm + arow) * KD + k0 + acol);
        float4 b4 = *(const float4*)(W + (size_t)(k0 + brow) * NN + bn + bcol);
        As[acol + 0][arow] = a4.x; As[acol + 1][arow] = a4.y;
        As[acol + 2][arow] = a4.z; As[acol + 3][arow] = a4.w;
        *(float4*)&Bs[brow][bcol] = b4;
        __syncthreads();
#pragma unroll
        for (int kk = 0; kk < 8; kk++) {
            float4 a0 = *(float4*)&As[kk][ty * 4];
            float4 a1 = *(float4*)&As[kk][64 + ty * 4];
            float4 b0 = *(float4*)&Bs[kk][tx * 4];
            float4 b1 = *(float4*)&Bs[kk][64 + tx * 4];
            float a[8] = {a0.x, a0.y, a0.z, a0.w, a1.x, a1.y, a1.z, a1.w};
            float b[8] = {b0.x, b0.y, b0.z, b0.w, b1.x, b1.y, b1.z, b1.w};
#pragma unroll
            for (int i = 0; i < 8; i++)
#pragma unroll
                for (int j = 0; j < 8; j++)
                    acc[i][j] = fmaf(a[i], b[j], acc[i][j]);
        }
        __syncthreads();
    }

#pragma unroll
    for (int i = 0; i < 8; i++) {
        int m = bm + ((i < 4) ? (ty * 4 + i) : (64 + ty * 4 + (i - 4)));
        int bb = m >> 10, tt = m & (T - 1);
#pragma unroll
        for (int jj = 0; jj < 2; jj++) {
            int n0 = bn + ((jj == 0) ? (tx * 4) : (64 + tx * 4));
            int hh = n0 >> 8, dd = n0 & (KD - 1);
            float4 o;
            o.x = acc[i][jj * 4 + 0] * scale;
            o.y = acc[i][jj * 4 + 1] * scale;
            o.z = acc[i][jj * 4 + 2] * scale;
            o.w = acc[i][jj * 4 + 3] * scale;
            *(float4*)(Out + ((((size_t)bb * H + hh) * T + tt) * KD + dd)) = o;
        }
    }
}

// ---------------------------------------------------------------------------
// Flash attention: one CTA = one (b,h) x 64-query tile, loops over 16 key
// tiles of 64. Q/K/V tiles (64x256 fp32 each) + P tile (64x64) in SMEM.
// K tile stores each float4 group g of row n at g ^ ((n>>2)&7) so the
// tx-strided QK^T reads are bank-conflict-free.
// ---------------------------------------------------------------------------
#define BR 64
#define BC 64

__global__ __launch_bounds__(256, 1) void attn_kernel()
{
    extern __shared__ float sm[];
    float* Qs = sm;                       // 64*256
    float* Ks = sm + BR * KD;             // 64*256 (swizzled)
    float* Vs = sm + 2 * BR * KD;         // 64*256
    float* Ps = sm + 3 * BR * KD;         // 64*64

    const int tid = threadIdx.x;
    const int tx = tid & 15, ty = tid >> 4;
    const int bh = blockIdx.y;
    const int q0 = blockIdx.x * BR;

    const float* Qg = g_Q + (size_t)bh * T * KD + (size_t)q0 * KD;
    const float* Kg = g_K + (size_t)bh * T * KD;
    const float* Vg = g_V + (size_t)bh * T * KD;

    // Load Q tile (natural layout, coalesced)
    for (int i = tid; i < BR * KD / 4; i += 256) {
        int r = i >> 6, g = i & 63;
        *(float4*)&Qs[r * KD + g * 4] = *(const float4*)(Qg + (size_t)r * KD + g * 4);
    }

    float m_i[4], l_i[4], o_acc[4][16];
#pragma unroll
    for (int i = 0; i < 4; i++) {
        m_i[i] = -CUDART_INF_F; l_i[i] = 0.f;
#pragma unroll
        for (int q = 0; q < 16; q++) o_acc[i][q] = 0.f;
    }
    __syncthreads();

    const int swz = tx & 7;

    for (int kt = 0; kt < T / BC; kt++) {
        const float* Kt = Kg + (size_t)kt * BC * KD;
        const float* Vt = Vg + (size_t)kt * BC * KD;
        // Load K (swizzled groups) and V (natural)
        for (int i = tid; i < BC * KD / 4; i += 256) {
            int n = i >> 6, g = i & 63;
            int pg = g ^ ((n >> 2) & 7);
            *(float4*)&Ks[n * KD + pg * 4] = *(const float4*)(Kt + (size_t)n * KD + g * 4);
            *(float4*)&Vs[n * KD + g * 4]  = *(const float4*)(Vt + (size_t)n * KD + g * 4);
        }
        __syncthreads();

        // S tile: rows ty*4+i, cols tx*4+j, contraction over 256 dims
        float s[4][4];
#pragma unroll
        for (int i = 0; i < 4; i++)
#pragma unroll
            for (int j = 0; j < 4; j++) s[i][j] = 0.f;

#pragma unroll 4
        for (int g = 0; g < 64; g++) {
            float4 a[4], bb4[4];
#pragma unroll
            for (int i = 0; i < 4; i++)
                a[i] = *(float4*)&Qs[(ty * 4 + i) * KD + g * 4];
            int pg4 = (g ^ swz) * 4;
#pragma unroll
            for (int j = 0; j < 4; j++)
                bb4[j] = *(float4*)&Ks[(tx * 4 + j) * KD + pg4];
#pragma unroll
            for (int i = 0; i < 4; i++)
#pragma unroll
                for (int j = 0; j < 4; j++) {
                    s[i][j] = fmaf(a[i].x, bb4[j].x, s[i][j]);
                    s[i][j] = fmaf(a[i].y, bb4[j].y, s[i][j]);
                    s[i][j] = fmaf(a[i].z, bb4[j].z, s[i][j]);
                    s[i][j] = fmaf(a[i].w, bb4[j].w, s[i][j]);
                }
        }

        // Online softmax (row groups are aligned 16-lane half-warps)
#pragma unroll
        for (int i = 0; i < 4; i++) {
            float mx = fmaxf(fmaxf(s[i][0], s[i][1]), fmaxf(s[i][2], s[i][3]));
            mx = fmaxf(mx, __shfl_xor_sync(0xffffffffu, mx, 1));
            mx = fmaxf(mx, __shfl_xor_sync(0xffffffffu, mx, 2));
            mx = fmaxf(mx, __shfl_xor_sync(0xffffffffu, mx, 4));
            mx = fmaxf(mx, __shfl_xor_sync(0xffffffffu, mx, 8));
            float m_new = fmaxf(m_i[i], mx);
            float corr  = __expf(m_i[i] - m_new);
            float rsum = 0.f;
#pragma unroll
            for (int j = 0; j < 4; j++) {
                s[i][j] = __expf(s[i][j] - m_new);
                rsum += s[i][j];
            }
            rsum += __shfl_xor_sync(0xffffffffu, rsum, 1);
            rsum += __shfl_xor_sync(0xffffffffu, rsum, 2);
            rsum += __shfl_xor_sync(0xffffffffu, rsum, 4);
            rsum += __shfl_xor_sync(0xffffffffu, rsum, 8);
            l_i[i] = l_i[i] * corr + rsum;
            m_i[i] = m_new;
#pragma unroll
            for (int q = 0; q < 16; q++) o_acc[i][q] *= corr;
        }

        // Publish P tile
#pragma unroll
        for (int i = 0; i < 4; i++) {
            float4 pv = make_float4(s[i][0], s[i][1], s[i][2], s[i][3]);
            *(float4*)&Ps[(ty * 4 + i) * 64 + tx * 4] = pv;
        }
        __syncthreads();

        // O += P @ V : rows ty*4+i, d-cols (tx + 16q)*4
#pragma unroll 2
        for (int c = 0; c < BC; c++) {
            float p[4];
#pragma unroll
            for (int i = 0; i < 4; i++) p[i] = Ps[(ty * 4 + i) * 64 + c];
#pragma unroll
            for (int q = 0; q < 4; q++) {
                float4 v = *(float4*)&Vs[c * KD + (tx + 16 * q) * 4];
#pragma unroll
                for (int i = 0; i < 4; i++) {
                    o_acc[i][q * 4 + 0] = fmaf(p[i], v.x, o_acc[i][q * 4 + 0]);
                    o_acc[i][q * 4 + 1] = fmaf(p[i], v.y, o_acc[i][q * 4 + 1]);
                    o_acc[i][q * 4 + 2] = fmaf(p[i], v.z, o_acc[i][q * 4 + 2]);
                    o_acc[i][q * 4 + 3] = fmaf(p[i], v.w, o_acc[i][q * 4 + 3]);
                }
            }
        }
        __syncthreads();
    }

    // Finalize and write to g_O [b, t, h*KD]
    const int bb = bh >> 3, hh = bh & 7;
#pragma unroll
    for (int i = 0; i < 4; i++) {
        float inv = 1.0f / l_i[i];
        int tt = q0 + ty * 4 + i;
        float* Og = g_O + ((size_t)bb * T + tt) * NN + hh * KD;
#pragma unroll
        for (int q = 0; q < 4; q++) {
            float4 o;
            o.x = o_acc[i][q * 4 + 0] * inv;
            o.y = o_acc[i][q * 4 + 1] * inv;
            o.z = o_acc[i][q * 4 + 2] * inv;
            o.w = o_acc[i][q * 4 + 3] * inv;
            *(float4*)(Og + (tx + 16 * q) * 4) = o;
        }
    }
}

// ---------------------------------------------------------------------------
// Output projection: out = g_O[8192,2048] @ Wu[2048,256] + bu
// ---------------------------------------------------------------------------
__global__ __launch_bounds__(256) void out_gemm(
    const float* __restrict__ Wu,
    const float* __restrict__ bu,
    float* __restrict__ C)
{
    __shared__ float As[8][128];
    __shared__ float Bs[8][128];

    const int bm = blockIdx.y * 128;
    const int bn = blockIdx.x * 128;
    const int tid  = threadIdx.x;
    const int arow = tid >> 1,  acol = (tid & 1) * 4;
    const int brow = tid >> 5,  bcol = (tid & 31) * 4;
    const int tx = tid & 15,    ty = tid >> 4;

    float acc[8][8];
#pragma unroll
    for (int i = 0; i < 8; i++)
#pragma unroll
        for (int j = 0; j < 8; j++) acc[i][j] = 0.f;

    for (int k0 = 0; k0 < NN; k0 += 8) {
        float4 a4 = *(const float4*)(g_O + (size_t)(bm + arow) * NN + k0 + acol);
        float4 b4 = *(const float4*)(Wu + (size_t)(k0 + brow) * KD + bn + bcol);
        As[acol + 0][arow] = a4.x; As[acol + 1][arow] = a4.y;
        As[acol + 2][arow] = a4.z; As[acol + 3][arow] = a4.w;
        *(float4*)&Bs[brow][bcol] = b4;
        __syncthreads();
#pragma unroll
        for (int kk = 0; kk < 8; kk++) {
            float4 a0 = *(float4*)&As[kk][ty * 4];
            float4 a1 = *(float4*)&As[kk][64 + ty * 4];
            float4 b0 = *(float4*)&Bs[kk][tx * 4];
            float4 b1 = *(float4*)&Bs[kk][64 + tx * 4];
            float a[8] = {a0.x, a0.y, a0.z, a0.w, a1.x, a1.y, a1.z, a1.w};
            float b[8] = {b0.x, b0.y, b0.z, b0.w, b1.x, b1.y, b1.z, b1.w};
#pragma unroll
            for (int i = 0; i < 8; i++)
#pragma unroll
                for (int j = 0; j < 8; j++)
                    acc[i][j] = fmaf(a[i], b[j], acc[i][j]);
        }
        __syncthreads();
    }

#pragma unroll
    for (int i = 0; i < 8; i++) {
        int m = bm + ((i < 4) ? (ty * 4 + i) : (64 + ty * 4 + (i - 4)));
#pragma unroll
        for (int jj = 0; jj < 2; jj++) {
            int n0 = bn + ((jj == 0) ? (tx * 4) : (64 + tx * 4));
            float4 bias = *(const float4*)(bu + n0);
            float4 o;
            o.x = acc[i][jj * 4 + 0] + bias.x;
            o.y = acc[i][jj * 4 + 1] + bias.y;
            o.z = acc[i][jj * 4 + 2] + bias.z;
            o.w = acc[i][jj * 4 + 3] + bias.w;
            *(float4*)(C + (size_t)m * KD + n0) = o;
        }
    }
}

// ---------------------------------------------------------------------------

extern "C" void kernel_launch(void* const* d_in, const int* in_sizes, int n_in,
                              void* d_out, int out_size)
{
    const float* x  = (const float*)d_in[0];
    const float* Wq = (const float*)d_in[1];
    const float* Wk = (const float*)d_in[2];
    const float* Wv = (const float*)d_in[3];
    const float* Wu = (const float*)d_in[4];
    const float* bu = (const float*)d_in[5];
    float* out = (float*)d_out;

    const int ATTN_SMEM = (3 * BR * KD + BR * BC) * (int)sizeof(float); // 212992 B
    cudaFuncSetAttribute(attn_kernel, cudaFuncAttributeMaxDynamicSharedMemorySize,
                         ATTN_SMEM);

    // 1) QKV projections (grid.z: 0=Q, 1=K, 2=V)
    dim3 g1(NN / 128, MM / 128, 3);
    qkv_gemm<<<g1, 256>>>(x, Wq, Wk, Wv);

    // 2) Flash attention: (q-tiles, b*h)
    dim3 g2(T / BR, B * H);
    attn_kernel<<<g2, 256, ATTN_SMEM>>>();

    // 3) Output projection + bias
    dim3 g3(KD / 128, MM / 128);
    out_gemm<<<g3, 256>>>(Wu, bu, out);
}

// round 11
// speedup vs baseline: 2.3992x; 2.3917x over previous
#include <cuda_runtime.h>
#include <cuda_fp16.h>
#include <cstdint>

#define BB   8
#define TT   1024
#define DD   256
#define HH   8
#define BH   (BB*HH)      // 64
#define MMALL (BB*TT)     // 8192
#define NNQKV (HH*DD)     // 2048

// ---------------------------------------------------------------------------
// Device scratch (no allocations allowed). 16B-aligned for half2/cp.async.
// ---------------------------------------------------------------------------
__device__ __align__(16) __half g_Xh [MMALL*DD];
__device__ __align__(16) __half g_Xl [MMALL*DD];
__device__ __align__(16) __half g_WTh[3*NNQKV*DD];      // [n=2048][k=256] per z
__device__ __align__(16) __half g_WTl[3*NNQKV*DD];
__device__ __align__(16) __half g_WuTh[DD*NNQKV];       // [n=256][k=2048]
__device__ __align__(16) __half g_WuTl[DD*NNQKV];
__device__ __align__(16) __half g_Qh [BH*TT*DD];        // [bh][t][d], x0.25
__device__ __align__(16) __half g_Ql [BH*TT*DD];
__device__ __align__(16) __half g_Kh [BH*TT*DD];
__device__ __align__(16) __half g_Kl [BH*TT*DD];
__device__ __align__(16) __half g_Vh [BH*TT*DD];        // [bh][t][d]
__device__ __align__(16) __half g_VT [BH*DD*TT];        // [bh][d][t]
__device__ __align__(16) __half g_Ph [(size_t)BH*TT*TT];// [bh][tq][ts] exp(s)
__device__ __align__(16) __half g_Oh [MMALL*NNQKV];     // [b*t][h*d]
__device__ __align__(16) __half g_Ol [MMALL*NNQKV];
__device__ float g_sums[BH*TT];

// ---------------------------------------------------------------------------
// PTX helpers (sm_80-era instructions only; valid at sm_103 base target)
// ---------------------------------------------------------------------------
__device__ __forceinline__ uint32_t smem_u32(const void* p){
    uint32_t a;
    asm("{ .reg .u64 t; cvta.to.shared.u64 t, %1; cvt.u32.u64 %0, t; }" : "=r"(a) : "l"(p));
    return a;
}
__device__ __forceinline__ void cp_async16(uint32_t dst, const __half* src){
    uint64_t g; asm("cvta.to.global.u64 %0, %1;" : "=l"(g) : "l"(src));
    asm volatile("cp.async.ca.shared.global [%0], [%1], 16;" :: "r"(dst), "l"(g));
}
__device__ __forceinline__ void cp_commit(){ asm volatile("cp.async.commit_group;" ::: "memory"); }
template<int N> __device__ __forceinline__ void cp_wait(){
    asm volatile("cp.async.wait_group %0;" :: "n"(N) : "memory");
}
__device__ __forceinline__ void ldsm4(uint32_t r[4], uint32_t addr){
    asm volatile("ldmatrix.sync.aligned.m8n8.x4.shared.b16 {%0,%1,%2,%3}, [%4];"
        : "=r"(r[0]), "=r"(r[1]), "=r"(r[2]), "=r"(r[3]) : "r"(addr));
}
__device__ __forceinline__ void mma16816(float c[4], const uint32_t a[4],
                                         uint32_t b0, uint32_t b1){
    asm volatile("mma.sync.aligned.m16n8k16.row.col.f32.f16.f16.f32 "
        "{%0,%1,%2,%3},{%4,%5,%6,%7},{%8,%9},{%0,%1,%2,%3};"
        : "+f"(c[0]), "+f"(c[1]), "+f"(c[2]), "+f"(c[3])
        : "r"(a[0]), "r"(a[1]), "r"(a[2]), "r"(a[3]), "r"(b0), "r"(b1));
}

// ---------------------------------------------------------------------------
// GEMM core: C[128,128] = A[128xK] @ B[128xK]^T (both K-major half).
// SPLIT: A/B given as (hi, lo) pairs; computes AhBh + AhBl + AlBh (fp32 acc).
// 256 threads = 8 warps (2x4 grid of 64x32 warp tiles). BK=32, 2-stage
// cp.async pipeline. SMEM rows padded to 144B -> conflict-free ldmatrix.
// ---------------------------------------------------------------------------
#define TILE_B   18432              // 128 rows * 144 bytes
#define SM3      (2*4*TILE_B)       // 147456
#define SM1      (2*2*TILE_B)       // 73728

template<bool SPLIT, class Epi>
__device__ __forceinline__ void gemm_core(
    const __half* __restrict__ Ah, const __half* __restrict__ Al, int lda,
    const __half* __restrict__ Bh, const __half* __restrict__ Bl, int ldb,
    int m0, int n0, int K, Epi&& epi)
{
    constexpr int NT = SPLIT ? 4 : 2;
    extern __shared__ __half smbuf[];
    const uint32_t smb = smem_u32(smbuf);
    const int tid  = threadIdx.x;
    const int lane = tid & 31, w = tid >> 5;

    // gmem->smem mapping: warp lanes -> 32 consecutive rows, fixed 16B chunk
    const int lrow = lane + 32 * (w & 3);
    const int lch0 = (w >> 2) * 2;          // chunks {0,1} or {2,3}

    float c[4][4][4];
#pragma unroll
    for (int i = 0; i < 4; i++)
#pragma unroll
        for (int j = 0; j < 4; j++)
#pragma unroll
            for (int q = 0; q < 4; q++) c[i][j][q] = 0.f;

    auto ldst = [&](int t, const __half* src, int ld, int rowbase, int k0, int buf){
        const __half* s = src + (size_t)(rowbase + lrow) * ld + k0 + lch0 * 8;
        uint32_t d = smb + (buf * NT + t) * TILE_B + lrow * 144 + lch0 * 16;
        cp_async16(d,      s);
        cp_async16(d + 16, s + 8);
    };
    auto load_stage = [&](int k0, int buf){
        ldst(0, Ah, lda, m0, k0, buf);
        ldst(1, Bh, ldb, n0, k0, buf);
        if (SPLIT) { ldst(2, Al, lda, m0, k0, buf); ldst(3, Bl, ldb, n0, k0, buf); }
        cp_commit();
    };

    const int wm = w & 1, wn = w >> 1;
    // lane address for ldmatrix.x4: lanes 0-15 -> 16 rows @k, lanes 16-31 -> +8 k
    const uint32_t lA = (uint32_t)(lane & 15) * 144 + (uint32_t)(lane >> 4) * 16;
    const uint32_t aOff = (uint32_t)(wm * 64) * 144 + lA;
    const uint32_t bOff = (uint32_t)(wn * 32) * 144 + lA;

    load_stage(0, 0);
    const int NST = K >> 5;
    for (int s = 0; s < NST; s++) {
        if (s + 1 < NST) { load_stage((s + 1) << 5, (s + 1) & 1); cp_wait<1>(); }
        else             { cp_wait<0>(); }
        __syncthreads();

        const int buf = s & 1;
        const uint32_t aHiB = smb + (buf * NT + 0) * TILE_B + aOff;
        const uint32_t bHiB = smb + (buf * NT + 1) * TILE_B + bOff;
        const uint32_t aLoB = SPLIT ? smb + (buf * NT + 2) * TILE_B + aOff : 0;
        const uint32_t bLoB = SPLIT ? smb + (buf * NT + 3) * TILE_B + bOff : 0;

#pragma unroll
        for (int k16 = 0; k16 < 2; k16++) {
            const uint32_t kb = k16 * 32;
            const int NP = SPLIT ? 3 : 1;
#pragma unroll
            for (int p = 0; p < NP; p++) {
                const uint32_t aB = (p == 2) ? aLoB : aHiB;
                const uint32_t bB = (p == 1) ? bLoB : bHiB;
                uint32_t a[4][4];
#pragma unroll
                for (int mi = 0; mi < 4; mi++) ldsm4(a[mi], aB + mi * 2304 + kb);
                uint32_t b[2][4];
#pragma unroll
                for (int nj = 0; nj < 2; nj++) ldsm4(b[nj], bB + nj * 2304 + kb);
#pragma unroll
                for (int mi = 0; mi < 4; mi++)
#pragma unroll
                    for (int ni = 0; ni < 4; ni++) {
                        const int nj = ni >> 1, sel = ni & 1;
                        mma16816(c[mi][ni], a[mi], b[nj][sel], b[nj][sel + 2]);
                    }
            }
        }
        __syncthreads();
    }

    // Epilogue: c frag (mi,ni): rows m0+wm*64+mi*16+(lane>>2)+{0,8},
    // cols n0+wn*32+ni*8+(lane&3)*2 (+1)
#pragma unroll
    for (int mi = 0; mi < 4; mi++)
#pragma unroll
        for (int h8 = 0; h8 < 2; h8++) {
            const int row = m0 + wm * 64 + mi * 16 + (lane >> 2) + h8 * 8;
#pragma unroll
            for (int ni = 0; ni < 4; ni++) {
                const int col = n0 + wn * 32 + ni * 8 + (lane & 3) * 2;
                epi(row, col, make_float2(c[mi][ni][h8 * 2], c[mi][ni][h8 * 2 + 1]));
            }
        }
}

// ---------------------------------------------------------------------------
// Pack / transpose kernels
// ---------------------------------------------------------------------------
__global__ void k_packx(const float* __restrict__ x){
    int i = blockIdx.x * 256 + threadIdx.x;
    float f = x[i];
    __half h = __float2half_rn(f);
    g_Xh[i] = h;
    g_Xl[i] = __float2half_rn(f - __half2float(h));
}

// W[R][C] fp32 -> (hi,lo) half [C][R]
__global__ void k_packw(const float* __restrict__ W, __half* __restrict__ oh,
                        __half* __restrict__ ol, int R, int C){
    __shared__ float t[32][33];
    int c0 = blockIdx.x * 32, r0 = blockIdx.y * 32;
    int x = threadIdx.x, y = threadIdx.y;
#pragma unroll
    for (int i = 0; i < 32; i += 8) t[y + i][x] = W[(size_t)(r0 + y + i) * C + c0 + x];
    __syncthreads();
#pragma unroll
    for (int i = 0; i < 32; i += 8) {
        float wv = t[x][y + i];
        __half h = __float2half_rn(wv);
        size_t o = (size_t)(c0 + y + i) * R + r0 + x;
        oh[o] = h;
        ol[o] = __float2half_rn(wv - __half2float(h));
    }
}

__global__ void k_vt(){
    __shared__ __half t[32][33];
    int bh = blockIdx.z;
    int d0 = blockIdx.x * 32, t0 = blockIdx.y * 32;
    int x = threadIdx.x, y = threadIdx.y;
    const __half* src = g_Vh + (size_t)bh * TT * DD;
    __half* dst = g_VT + (size_t)bh * DD * TT;
#pragma unroll
    for (int i = 0; i < 32; i += 8) t[y + i][x] = src[(size_t)(t0 + y + i) * DD + d0 + x];
    __syncthreads();
#pragma unroll
    for (int i = 0; i < 32; i += 8) dst[(size_t)(d0 + y + i) * TT + t0 + x] = t[x][y + i];
}

__global__ void k_zero(){
    int i = blockIdx.x * 1024 + threadIdx.x;
    if (i < BH * TT) g_sums[i] = 0.f;
}

// ---------------------------------------------------------------------------
// GEMM kernels
// ---------------------------------------------------------------------------
__global__ __launch_bounds__(256) void k_qkv(){
    const int z = blockIdx.z;
    const int m0 = blockIdx.y * 128, n0 = blockIdx.x * 128;
    const __half* Bh_ = g_WTh + (size_t)z * NNQKV * DD;
    const __half* Bl_ = g_WTl + (size_t)z * NNQKV * DD;
    gemm_core<true>(g_Xh, g_Xl, DD, Bh_, Bl_, DD, m0, n0, DD,
        [&](int row, int col, float2 v){
            int b = row >> 10, t = row & 1023, h = col >> 8, d = col & 255;
            size_t o = ((size_t)(b * HH + h) * TT + t) * DD + d;
            if (z == 2) {
                *reinterpret_cast<__half2*>(&g_Vh[o]) =
                    __halves2half2(__float2half_rn(v.x), __float2half_rn(v.y));
            } else {
                float qx = v.x * 0.25f, qy = v.y * 0.25f;
                __half hx = __float2half_rn(qx), hy = __float2half_rn(qy);
                __half lx = __float2half_rn(qx - __half2float(hx));
                __half ly = __float2half_rn(qy - __half2float(hy));
                __half* Hh = (z == 0) ? g_Qh : g_Kh;
                __half* Hl = (z == 0) ? g_Ql : g_Kl;
                *reinterpret_cast<__half2*>(&Hh[o]) = __halves2half2(hx, hy);
                *reinterpret_cast<__half2*>(&Hl[o]) = __halves2half2(lx, ly);
            }
        });
}

__global__ __launch_bounds__(256) void k_score(){
    const int bh = blockIdx.z;
    const int m0 = blockIdx.y * 128, n0 = blockIdx.x * 128;
    const size_t off = (size_t)bh * TT * DD;
    const int lane = threadIdx.x & 31;
    gemm_core<true>(g_Qh + off, g_Ql + off, DD, g_Kh + off, g_Kl + off, DD,
        m0, n0, DD,
        [&](int row, int col, float2 v){
            float px = __expf(v.x), py = __expf(v.y);
            __half hx = __float2half_rn(px), hy = __float2half_rn(py);
            size_t o = ((size_t)bh * TT + row) * TT + col;
            *reinterpret_cast<__half2*>(&g_Ph[o]) = __halves2half2(hx, hy);
            float sum = __half2float(hx) + __half2float(hy);
            sum += __shfl_xor_sync(0xffffffffu, sum, 1);
            sum += __shfl_xor_sync(0xffffffffu, sum, 2);
            if ((lane & 3) == 0) atomicAdd(&g_sums[bh * TT + row], sum);
        });
}

__global__ __launch_bounds__(256) void k_pv(){
    const int bh = blockIdx.z;
    const int m0 = blockIdx.y * 128, n0 = blockIdx.x * 128;
    const __half* A = g_Ph + (size_t)bh * TT * TT;
    const __half* Bp = g_VT + (size_t)bh * DD * TT;
    gemm_core<false>(A, nullptr, TT, Bp, nullptr, TT, m0, n0, TT,
        [&](int row, int col, float2 v){
            int b = bh >> 3, h = bh & 7;
            float inv = 1.0f / g_sums[bh * TT + row];
            float ox = v.x * inv, oy = v.y * inv;
            __half hx = __float2half_rn(ox), hy = __float2half_rn(oy);
            __half lx = __float2half_rn(ox - __half2float(hx));
            __half ly = __float2half_rn(oy - __half2float(hy));
            size_t o = (size_t)(b * TT + row) * NNQKV + h * DD + col;
            *reinterpret_cast<__half2*>(&g_Oh[o]) = __halves2half2(hx, hy);
            *reinterpret_cast<__half2*>(&g_Ol[o]) = __halves2half2(lx, ly);
        });
}

__global__ __launch_bounds__(256) void k_out(const float* __restrict__ bu,
                                             float* __restrict__ Cout){
    const int m0 = blockIdx.y * 128, n0 = blockIdx.x * 128;
    gemm_core<true>(g_Oh, g_Ol, NNQKV, g_WuTh, g_WuTl, NNQKV, m0, n0, NNQKV,
        [&](int row, int col, float2 v){
            float2 b2 = *reinterpret_cast<const float2*>(bu + col);
            float2 o = make_float2(v.x + b2.x, v.y + b2.y);
            *reinterpret_cast<float2*>(Cout + (size_t)row * DD + col) = o;
        });
}

// ---------------------------------------------------------------------------
extern "C" void kernel_launch(void* const* d_in, const int* in_sizes, int n_in,
                              void* d_out, int out_size)
{
    const float* x  = (const float*)d_in[0];
    const float* Wq = (const float*)d_in[1];
    const float* Wk = (const float*)d_in[2];
    const float* Wv = (const float*)d_in[3];
    const float* Wu = (const float*)d_in[4];
    const float* bu = (const float*)d_in[5];
    float* out = (float*)d_out;

    static bool attr_done = false;
    cudaFuncSetAttribute(k_qkv,   cudaFuncAttributeMaxDynamicSharedMemorySize, SM3);
    cudaFuncSetAttribute(k_score, cudaFuncAttributeMaxDynamicSharedMemorySize, SM3);
    cudaFuncSetAttribute(k_pv,    cudaFuncAttributeMaxDynamicSharedMemorySize, SM1);
    cudaFuncSetAttribute(k_out,   cudaFuncAttributeMaxDynamicSharedMemorySize, SM3);
    (void)attr_done;

    __half *pWTh, *pWTl, *pWuTh, *pWuTl;
    cudaGetSymbolAddress((void**)&pWTh,  g_WTh);
    cudaGetSymbolAddress((void**)&pWTl,  g_WTl);
    cudaGetSymbolAddress((void**)&pWuTh, g_WuTh);
    cudaGetSymbolAddress((void**)&pWuTl, g_WuTl);

    dim3 tb(32, 8);
    k_packx<<<MMALL * DD / 256, 256>>>(x);
    k_packw<<<dim3(NNQKV / 32, DD / 32), tb>>>(Wq, pWTh,                 pWTl,                 DD, NNQKV);
    k_packw<<<dim3(NNQKV / 32, DD / 32), tb>>>(Wk, pWTh + NNQKV * DD,    pWTl + NNQKV * DD,    DD, NNQKV);
    k_packw<<<dim3(NNQKV / 32, DD / 32), tb>>>(Wv, pWTh + 2 * NNQKV * DD, pWTl + 2 * NNQKV * DD, DD, NNQKV);
    k_packw<<<dim3(DD / 32, NNQKV / 32), tb>>>(Wu, pWuTh,                pWuTl,                NNQKV, DD);
    k_zero<<<64, 1024>>>();

    k_qkv  <<<dim3(NNQKV / 128, MMALL / 128, 3), 256, SM3>>>();
    k_vt   <<<dim3(DD / 32, TT / 32, BH), tb>>>();
    k_score<<<dim3(TT / 128, TT / 128, BH), 256, SM3>>>();
    k_pv   <<<dim3(DD / 128, TT / 128, BH), 256, SM1>>>();
    k_out  <<<dim3(DD / 128, MMALL / 128, 1), 256, SM3>>>(bu, out);
}

// round 12
// speedup vs baseline: 2.5542x; 1.0646x over previous
#include <cuda_runtime.h>
#include <cuda_fp16.h>
#include <cstdint>

#define BB   8
#define TT   1024
#define DD   256
#define HH   8
#define BH   (BB*HH)      // 64
#define MMALL (BB*TT)     // 8192
#define NNQKV (HH*DD)     // 2048

// ---------------------------------------------------------------------------
// Device scratch (no allocations allowed). 16B-aligned for half2/cp.async.
// ---------------------------------------------------------------------------
__device__ __align__(16) __half g_Xh [MMALL*DD];
__device__ __align__(16) __half g_Xl [MMALL*DD];
__device__ __align__(16) __half g_WTh[3*NNQKV*DD];      // [n=2048][k=256] per z
__device__ __align__(16) __half g_WTl[3*NNQKV*DD];
__device__ __align__(16) __half g_WuTh[DD*NNQKV];       // [n=256][k=2048]
__device__ __align__(16) __half g_WuTl[DD*NNQKV];
__device__ __align__(16) __half g_Qh [BH*TT*DD];        // [bh][t][d], x0.25
__device__ __align__(16) __half g_Ql [BH*TT*DD];
__device__ __align__(16) __half g_Kh [BH*TT*DD];
__device__ __align__(16) __half g_Kl [BH*TT*DD];
__device__ __align__(16) __half g_Vh [BH*TT*DD];        // [bh][t][d]
__device__ __align__(16) __half g_VT [BH*DD*TT];        // [bh][d][t]
__device__ __align__(16) __half g_Ph [(size_t)BH*TT*TT];// [bh][tq][ts] exp(s)
__device__ __align__(16) __half g_Oh [MMALL*NNQKV];     // [b*t][h*d]
__device__ __align__(16) __half g_Ol [MMALL*NNQKV];
__device__ float g_sums[BH*TT];

// ---------------------------------------------------------------------------
// PTX helpers (sm_80-era instructions only; valid at sm_103 base target)
// ---------------------------------------------------------------------------
__device__ __forceinline__ uint32_t smem_u32(const void* p){
    uint32_t a;
    asm("{ .reg .u64 t; cvta.to.shared.u64 t, %1; cvt.u32.u64 %0, t; }" : "=r"(a) : "l"(p));
    return a;
}
__device__ __forceinline__ void cp_async16(uint32_t dst, const __half* src){
    uint64_t g; asm("cvta.to.global.u64 %0, %1;" : "=l"(g) : "l"(src));
    asm volatile("cp.async.ca.shared.global [%0], [%1], 16;" :: "r"(dst), "l"(g));
}
__device__ __forceinline__ void cp_commit(){ asm volatile("cp.async.commit_group;" ::: "memory"); }
template<int N> __device__ __forceinline__ void cp_wait(){
    asm volatile("cp.async.wait_group %0;" :: "n"(N) : "memory");
}
__device__ __forceinline__ void ldsm4(uint32_t r[4], uint32_t addr){
    asm volatile("ldmatrix.sync.aligned.m8n8.x4.shared.b16 {%0,%1,%2,%3}, [%4];"
        : "=r"(r[0]), "=r"(r[1]), "=r"(r[2]), "=r"(r[3]) : "r"(addr));
}
__device__ __forceinline__ void mma16816(float c[4], const uint32_t a[4],
                                         uint32_t b0, uint32_t b1){
    asm volatile("mma.sync.aligned.m16n8k16.row.col.f32.f16.f16.f32 "
        "{%0,%1,%2,%3},{%4,%5,%6,%7},{%8,%9},{%0,%1,%2,%3};"
        : "+f"(c[0]), "+f"(c[1]), "+f"(c[2]), "+f"(c[3])
        : "r"(a[0]), "r"(a[1]), "r"(a[2]), "r"(a[3]), "r"(b0), "r"(b1));
}

// ---------------------------------------------------------------------------
// GEMM core: C[128,128] = A[128xK] @ B[128xK]^T (both K-major half).
// SPLIT: A/B given as (hi, lo) pairs; computes AhBh + AhBl + AlBh (fp32 acc).
// 256 threads = 8 warps (2x4 grid of 64x32 warp tiles). BK=32, 2-stage
// cp.async pipeline. SMEM row stride 80B (=16*5, odd multiple of 16) ->
// conflict-free ldmatrix AND small enough for 2 CTAs/SM on split kernels.
// ---------------------------------------------------------------------------
#define ROWB     80
#define TILE_B   (128*ROWB)         // 10240
#define SM3      (2*4*TILE_B)       // 81920  -> 2 CTAs/SM
#define SM1      (2*2*TILE_B)       // 40960

template<bool SPLIT, class Epi>
__device__ __forceinline__ void gemm_core(
    const __half* __restrict__ Ah, const __half* __restrict__ Al, int lda,
    const __half* __restrict__ Bh, const __half* __restrict__ Bl, int ldb,
    int m0, int n0, int K, Epi&& epi)
{
    constexpr int NT = SPLIT ? 4 : 2;
    extern __shared__ __half smbuf[];
    const uint32_t smb = smem_u32(smbuf);
    const int tid  = threadIdx.x;
    const int lane = tid & 31, w = tid >> 5;

    // gmem->smem mapping: warp lanes -> 32 consecutive rows, fixed 16B chunk
    const int lrow = lane + 32 * (w & 3);
    const int lch0 = (w >> 2) * 2;          // chunks {0,1} or {2,3}

    float c[4][4][4];
#pragma unroll
    for (int i = 0; i < 4; i++)
#pragma unroll
        for (int j = 0; j < 4; j++)
#pragma unroll
            for (int q = 0; q < 4; q++) c[i][j][q] = 0.f;

    auto ldst = [&](int t, const __half* src, int ld, int rowbase, int k0, int buf){
        const __half* s = src + (size_t)(rowbase + lrow) * ld + k0 + lch0 * 8;
        uint32_t d = smb + (buf * NT + t) * TILE_B + lrow * ROWB + lch0 * 16;
        cp_async16(d,      s);
        cp_async16(d + 16, s + 8);
    };
    auto load_stage = [&](int k0, int buf){
        ldst(0, Ah, lda, m0, k0, buf);
        ldst(1, Bh, ldb, n0, k0, buf);
        if (SPLIT) { ldst(2, Al, lda, m0, k0, buf); ldst(3, Bl, ldb, n0, k0, buf); }
        cp_commit();
    };

    const int wm = w & 1, wn = w >> 1;
    // lane address for ldmatrix.x4: lanes 0-15 -> 16 rows @k, lanes 16-31 -> +8 k
    const uint32_t lA = (uint32_t)(lane & 15) * ROWB + (uint32_t)(lane >> 4) * 16;
    const uint32_t aOff = (uint32_t)(wm * 64) * ROWB + lA;
    const uint32_t bOff = (uint32_t)(wn * 32) * ROWB + lA;

    load_stage(0, 0);
    const int NST = K >> 5;
    for (int s = 0; s < NST; s++) {
        if (s + 1 < NST) { load_stage((s + 1) << 5, (s + 1) & 1); cp_wait<1>(); }
        else             { cp_wait<0>(); }
        __syncthreads();

        const int buf = s & 1;
        const uint32_t aHiB = smb + (buf * NT + 0) * TILE_B + aOff;
        const uint32_t bHiB = smb + (buf * NT + 1) * TILE_B + bOff;
        const uint32_t aLoB = SPLIT ? smb + (buf * NT + 2) * TILE_B + aOff : 0;
        const uint32_t bLoB = SPLIT ? smb + (buf * NT + 3) * TILE_B + bOff : 0;

#pragma unroll
        for (int k16 = 0; k16 < 2; k16++) {
            const uint32_t kb = k16 * 32;
            const int NP = SPLIT ? 3 : 1;
#pragma unroll
            for (int p = 0; p < NP; p++) {
                const uint32_t aB = (p == 2) ? aLoB : aHiB;
                const uint32_t bB = (p == 1) ? bLoB : bHiB;
                uint32_t a[4][4];
#pragma unroll
                for (int mi = 0; mi < 4; mi++) ldsm4(a[mi], aB + mi * (16*ROWB) + kb);
                uint32_t b[2][4];
#pragma unroll
                for (int nj = 0; nj < 2; nj++) ldsm4(b[nj], bB + nj * (16*ROWB) + kb);
#pragma unroll
                for (int mi = 0; mi < 4; mi++)
#pragma unroll
                    for (int ni = 0; ni < 4; ni++) {
                        const int nj = ni >> 1, sel = ni & 1;
                        mma16816(c[mi][ni], a[mi], b[nj][sel], b[nj][sel + 2]);
                    }
            }
        }
        __syncthreads();
    }

    // Epilogue: c frag (mi,ni): rows m0+wm*64+mi*16+(lane>>2)+{0,8},
    // cols n0+wn*32+ni*8+(lane&3)*2 (+1)
#pragma unroll
    for (int mi = 0; mi < 4; mi++)
#pragma unroll
        for (int h8 = 0; h8 < 2; h8++) {
            const int row = m0 + wm * 64 + mi * 16 + (lane >> 2) + h8 * 8;
#pragma unroll
            for (int ni = 0; ni < 4; ni++) {
                const int col = n0 + wn * 32 + ni * 8 + (lane & 3) * 2;
                epi(row, col, make_float2(c[mi][ni][h8 * 2], c[mi][ni][h8 * 2 + 1]));
            }
        }
}

// ---------------------------------------------------------------------------
// Pack / transpose kernels
// ---------------------------------------------------------------------------
__global__ void k_packx(const float* __restrict__ x){
    int i = blockIdx.x * 256 + threadIdx.x;
    float f = x[i];
    __half h = __float2half_rn(f);
    g_Xh[i] = h;
    g_Xl[i] = __float2half_rn(f - __half2float(h));
}

// W[R][C] fp32 -> (hi,lo) half [C][R]
__global__ void k_packw(const float* __restrict__ W, __half* __restrict__ oh,
                        __half* __restrict__ ol, int R, int C){
    __shared__ float t[32][33];
    int c0 = blockIdx.x * 32, r0 = blockIdx.y * 32;
    int x = threadIdx.x, y = threadIdx.y;
#pragma unroll
    for (int i = 0; i < 32; i += 8) t[y + i][x] = W[(size_t)(r0 + y + i) * C + c0 + x];
    __syncthreads();
#pragma unroll
    for (int i = 0; i < 32; i += 8) {
        float wv = t[x][y + i];
        __half h = __float2half_rn(wv);
        size_t o = (size_t)(c0 + y + i) * R + r0 + x;
        oh[o] = h;
        ol[o] = __float2half_rn(wv - __half2float(h));
    }
}

__global__ void k_vt(){
    __shared__ __half t[32][33];
    int bh = blockIdx.z;
    int d0 = blockIdx.x * 32, t0 = blockIdx.y * 32;
    int x = threadIdx.x, y = threadIdx.y;
    const __half* src = g_Vh + (size_t)bh * TT * DD;
    __half* dst = g_VT + (size_t)bh * DD * TT;
#pragma unroll
    for (int i = 0; i < 32; i += 8) t[y + i][x] = src[(size_t)(t0 + y + i) * DD + d0 + x];
    __syncthreads();
#pragma unroll
    for (int i = 0; i < 32; i += 8) dst[(size_t)(d0 + y + i) * TT + t0 + x] = t[x][y + i];
}

__global__ void k_zero(){
    int i = blockIdx.x * 1024 + threadIdx.x;
    if (i < BH * TT) g_sums[i] = 0.f;
}

// ---------------------------------------------------------------------------
// GEMM kernels
// ---------------------------------------------------------------------------
__global__ __launch_bounds__(256, 2) void k_qkv(){
    const int z = blockIdx.z;
    const int m0 = blockIdx.y * 128, n0 = blockIdx.x * 128;
    const __half* Bh_ = g_WTh + (size_t)z * NNQKV * DD;
    const __half* Bl_ = g_WTl + (size_t)z * NNQKV * DD;
    gemm_core<true>(g_Xh, g_Xl, DD, Bh_, Bl_, DD, m0, n0, DD,
        [&](int row, int col, float2 v){
            int b = row >> 10, t = row & 1023, h = col >> 8, d = col & 255;
            size_t o = ((size_t)(b * HH + h) * TT + t) * DD + d;
            if (z == 2) {
                *reinterpret_cast<__half2*>(&g_Vh[o]) =
                    __halves2half2(__float2half_rn(v.x), __float2half_rn(v.y));
            } else {
                float qx = v.x * 0.25f, qy = v.y * 0.25f;
                __half hx = __float2half_rn(qx), hy = __float2half_rn(qy);
                __half lx = __float2half_rn(qx - __half2float(hx));
                __half ly = __float2half_rn(qy - __half2float(hy));
                __half* Hh = (z == 0) ? g_Qh : g_Kh;
                __half* Hl = (z == 0) ? g_Ql : g_Kl;
                *reinterpret_cast<__half2*>(&Hh[o]) = __halves2half2(hx, hy);
                *reinterpret_cast<__half2*>(&Hl[o]) = __halves2half2(lx, ly);
            }
        });
}

__global__ __launch_bounds__(256, 2) void k_score(){
    const int bh = blockIdx.z;
    const int m0 = blockIdx.y * 128, n0 = blockIdx.x * 128;
    const size_t off = (size_t)bh * TT * DD;
    const int lane = threadIdx.x & 31;
    gemm_core<true>(g_Qh + off, g_Ql + off, DD, g_Kh + off, g_Kl + off, DD,
        m0, n0, DD,
        [&](int row, int col, float2 v){
            float px = __expf(v.x), py = __expf(v.y);
            __half hx = __float2half_rn(px), hy = __float2half_rn(py);
            size_t o = ((size_t)bh * TT + row) * TT + col;
            *reinterpret_cast<__half2*>(&g_Ph[o]) = __halves2half2(hx, hy);
            float sum = __half2float(hx) + __half2float(hy);
            sum += __shfl_xor_sync(0xffffffffu, sum, 1);
            sum += __shfl_xor_sync(0xffffffffu, sum, 2);
            if ((lane & 3) == 0) atomicAdd(&g_sums[bh * TT + row], sum);
        });
}

__global__ __launch_bounds__(256, 2) void k_pv(){
    const int bh = blockIdx.z;
    const int m0 = blockIdx.y * 128, n0 = blockIdx.x * 128;
    const __half* A = g_Ph + (size_t)bh * TT * TT;
    const __half* Bp = g_VT + (size_t)bh * DD * TT;
    gemm_core<false>(A, nullptr, TT, Bp, nullptr, TT, m0, n0, TT,
        [&](int row, int col, float2 v){
            int b = bh >> 3, h = bh & 7;
            float inv = 1.0f / g_sums[bh * TT + row];
            float ox = v.x * inv, oy = v.y * inv;
            __half hx = __float2half_rn(ox), hy = __float2half_rn(oy);
            __half lx = __float2half_rn(ox - __half2float(hx));
            __half ly = __float2half_rn(oy - __half2float(hy));
            size_t o = (size_t)(b * TT + row) * NNQKV + h * DD + col;
            *reinterpret_cast<__half2*>(&g_Oh[o]) = __halves2half2(hx, hy);
            *reinterpret_cast<__half2*>(&g_Ol[o]) = __halves2half2(lx, ly);
        });
}

__global__ __launch_bounds__(256, 2) void k_out(const float* __restrict__ bu,
                                                float* __restrict__ Cout){
    const int m0 = blockIdx.y * 128, n0 = blockIdx.x * 128;
    gemm_core<true>(g_Oh, g_Ol, NNQKV, g_WuTh, g_WuTl, NNQKV, m0, n0, NNQKV,
        [&](int row, int col, float2 v){
            float2 b2 = *reinterpret_cast<const float2*>(bu + col);
            float2 o = make_float2(v.x + b2.x, v.y + b2.y);
            *reinterpret_cast<float2*>(Cout + (size_t)row * DD + col) = o;
        });
}

// ---------------------------------------------------------------------------
extern "C" void kernel_launch(void* const* d_in, const int* in_sizes, int n_in,
                              void* d_out, int out_size)
{
    const float* x  = (const float*)d_in[0];
    const float* Wq = (const float*)d_in[1];
    const float* Wk = (const float*)d_in[2];
    const float* Wv = (const float*)d_in[3];
    const float* Wu = (const float*)d_in[4];
    const float* bu = (const float*)d_in[5];
    float* out = (float*)d_out;

    cudaFuncSetAttribute(k_qkv,   cudaFuncAttributeMaxDynamicSharedMemorySize, SM3);
    cudaFuncSetAttribute(k_score, cudaFuncAttributeMaxDynamicSharedMemorySize, SM3);
    cudaFuncSetAttribute(k_pv,    cudaFuncAttributeMaxDynamicSharedMemorySize, SM1);
    cudaFuncSetAttribute(k_out,   cudaFuncAttributeMaxDynamicSharedMemorySize, SM3);

    __half *pWTh, *pWTl, *pWuTh, *pWuTl;
    cudaGetSymbolAddress((void**)&pWTh,  g_WTh);
    cudaGetSymbolAddress((void**)&pWTl,  g_WTl);
    cudaGetSymbolAddress((void**)&pWuTh, g_WuTh);
    cudaGetSymbolAddress((void**)&pWuTl, g_WuTl);

    dim3 tb(32, 8);
    k_packx<<<MMALL * DD / 256, 256>>>(x);
    k_packw<<<dim3(NNQKV / 32, DD / 32), tb>>>(Wq, pWTh,                 pWTl,                 DD, NNQKV);
    k_packw<<<dim3(NNQKV / 32, DD / 32), tb>>>(Wk, pWTh + NNQKV * DD,    pWTl + NNQKV * DD,    DD, NNQKV);
    k_packw<<<dim3(NNQKV / 32, DD / 32), tb>>>(Wv, pWTh + 2 * NNQKV * DD, pWTl + 2 * NNQKV * DD, DD, NNQKV);
    k_packw<<<dim3(DD / 32, NNQKV / 32), tb>>>(Wu, pWuTh,                pWuTl,                NNQKV, DD);
    k_zero<<<64, 1024>>>();

    k_qkv  <<<dim3(NNQKV / 128, MMALL / 128, 3), 256, SM3>>>();
    k_vt   <<<dim3(DD / 32, TT / 32, BH), tb>>>();
    k_score<<<dim3(TT / 128, TT / 128, BH), 256, SM3>>>();
    k_pv   <<<dim3(DD / 128, TT / 128, BH), 256, SM1>>>();
    k_out  <<<dim3(DD / 128, MMALL / 128, 1), 256, SM3>>>(bu, out);
}

// round 13
// speedup vs baseline: 3.6810x; 1.4411x over previous
#include <cuda_runtime.h>
#include <cuda_fp16.h>
#include <cstdint>

#define BB   8
#define TT   1024
#define DD   256
#define HH   8
#define BH   (BB*HH)      // 64
#define MMALL (BB*TT)     // 8192
#define NNQKV (HH*DD)     // 2048

// ---------------------------------------------------------------------------
// Device scratch (no allocations allowed). 16B-aligned for half2/cp.async.
// ---------------------------------------------------------------------------
__device__ __align__(16) __half g_Xh [MMALL*DD];
__device__ __align__(16) __half g_Xl [MMALL*DD];
__device__ __align__(16) __half g_WTh[3*NNQKV*DD];      // [n=2048][k=256] per z
__device__ __align__(16) __half g_WTl[3*NNQKV*DD];
__device__ __align__(16) __half g_WuTh[DD*NNQKV];       // [n=256][k=2048]
__device__ __align__(16) __half g_WuTl[DD*NNQKV];
__device__ __align__(16) __half g_Qh [BH*TT*DD];        // [bh][t][d], x0.25
__device__ __align__(16) __half g_Kh [BH*TT*DD];        // [bh][t][d], x0.25
__device__ __align__(16) __half g_Vh [BH*TT*DD];        // [bh][t][d]
__device__ __align__(16) __half g_VT [BH*DD*TT];        // [bh][d][t]
__device__ __align__(16) __half g_Oh [MMALL*NNQKV];     // [b*t][h*d]
__device__ __align__(16) __half g_Ol [MMALL*NNQKV];

// ---------------------------------------------------------------------------
// PTX helpers (sm_80-era instructions only; valid at sm_103 base target)
// ---------------------------------------------------------------------------
__device__ __forceinline__ uint32_t smem_u32(const void* p){
    uint32_t a;
    asm("{ .reg .u64 t; cvta.to.shared.u64 t, %1; cvt.u32.u64 %0, t; }" : "=r"(a) : "l"(p));
    return a;
}
__device__ __forceinline__ void cp_async16(uint32_t dst, const __half* src){
    uint64_t g; asm("cvta.to.global.u64 %0, %1;" : "=l"(g) : "l"(src));
    asm volatile("cp.async.ca.shared.global [%0], [%1], 16;" :: "r"(dst), "l"(g));
}
__device__ __forceinline__ void cp_commit(){ asm volatile("cp.async.commit_group;" ::: "memory"); }
template<int N> __device__ __forceinline__ void cp_wait(){
    asm volatile("cp.async.wait_group %0;" :: "n"(N) : "memory");
}
__device__ __forceinline__ void ldsm4(uint32_t r[4], uint32_t addr){
    asm volatile("ldmatrix.sync.aligned.m8n8.x4.shared.b16 {%0,%1,%2,%3}, [%4];"
        : "=r"(r[0]), "=r"(r[1]), "=r"(r[2]), "=r"(r[3]) : "r"(addr));
}
__device__ __forceinline__ void mma16816(float c[4], const uint32_t a[4],
                                         uint32_t b0, uint32_t b1){
    asm volatile("mma.sync.aligned.m16n8k16.row.col.f32.f16.f16.f32 "
        "{%0,%1,%2,%3},{%4,%5,%6,%7},{%8,%9},{%0,%1,%2,%3};"
        : "+f"(c[0]), "+f"(c[1]), "+f"(c[2]), "+f"(c[3])
        : "r"(a[0]), "r"(a[1]), "r"(a[2]), "r"(a[3]), "r"(b0), "r"(b1));
}

// ---------------------------------------------------------------------------
// GEMM core (for projections): C[128,128] = A[128xK] @ B[128xK]^T.
// SPLIT: (hi,lo) pairs; AhBh + AhBl + AlBh, fp32 acc. 8 warps (2x4, 64x32).
// BK=32, 2-stage cp.async. Row stride 80B -> conflict-free + 2 CTAs/SM.
// ---------------------------------------------------------------------------
#define ROWB     80
#define TILE_B   (128*ROWB)         // 10240
#define SM3      (2*4*TILE_B)       // 81920

template<bool SPLIT, class Epi>
__device__ __forceinline__ void gemm_core(
    const __half* __restrict__ Ah, const __half* __restrict__ Al, int lda,
    const __half* __restrict__ Bh, const __half* __restrict__ Bl, int ldb,
    int m0, int n0, int K, Epi&& epi)
{
    constexpr int NT = SPLIT ? 4 : 2;
    extern __shared__ __half smbuf[];
    const uint32_t smb = smem_u32(smbuf);
    const int tid  = threadIdx.x;
    const int lane = tid & 31, w = tid >> 5;

    const int lrow = lane + 32 * (w & 3);
    const int lch0 = (w >> 2) * 2;

    float c[4][4][4];
#pragma unroll
    for (int i = 0; i < 4; i++)
#pragma unroll
        for (int j = 0; j < 4; j++)
#pragma unroll
            for (int q = 0; q < 4; q++) c[i][j][q] = 0.f;

    auto ldst = [&](int t, const __half* src, int ld, int rowbase, int k0, int buf){
        const __half* s = src + (size_t)(rowbase + lrow) * ld + k0 + lch0 * 8;
        uint32_t d = smb + (buf * NT + t) * TILE_B + lrow * ROWB + lch0 * 16;
        cp_async16(d,      s);
        cp_async16(d + 16, s + 8);
    };
    auto load_stage = [&](int k0, int buf){
        ldst(0, Ah, lda, m0, k0, buf);
        ldst(1, Bh, ldb, n0, k0, buf);
        if (SPLIT) { ldst(2, Al, lda, m0, k0, buf); ldst(3, Bl, ldb, n0, k0, buf); }
        cp_commit();
    };

    const int wm = w & 1, wn = w >> 1;
    const uint32_t lA = (uint32_t)(lane & 15) * ROWB + (uint32_t)(lane >> 4) * 16;
    const uint32_t aOff = (uint32_t)(wm * 64) * ROWB + lA;
    const uint32_t bOff = (uint32_t)(wn * 32) * ROWB + lA;

    load_stage(0, 0);
    const int NST = K >> 5;
    for (int s = 0; s < NST; s++) {
        if (s + 1 < NST) { load_stage((s + 1) << 5, (s + 1) & 1); cp_wait<1>(); }
        else             { cp_wait<0>(); }
        __syncthreads();

        const int buf = s & 1;
        const uint32_t aHiB = smb + (buf * NT + 0) * TILE_B + aOff;
        const uint32_t bHiB = smb + (buf * NT + 1) * TILE_B + bOff;
        const uint32_t aLoB = SPLIT ? smb + (buf * NT + 2) * TILE_B + aOff : 0;
        const uint32_t bLoB = SPLIT ? smb + (buf * NT + 3) * TILE_B + bOff : 0;

#pragma unroll
        for (int k16 = 0; k16 < 2; k16++) {
            const uint32_t kb = k16 * 32;
            const int NP = SPLIT ? 3 : 1;
#pragma unroll
            for (int p = 0; p < NP; p++) {
                const uint32_t aB = (p == 2) ? aLoB : aHiB;
                const uint32_t bB = (p == 1) ? bLoB : bHiB;
                uint32_t a[4][4];
#pragma unroll
                for (int mi = 0; mi < 4; mi++) ldsm4(a[mi], aB + mi * (16*ROWB) + kb);
                uint32_t b[2][4];
#pragma unroll
                for (int nj = 0; nj < 2; nj++) ldsm4(b[nj], bB + nj * (16*ROWB) + kb);
#pragma unroll
                for (int mi = 0; mi < 4; mi++)
#pragma unroll
                    for (int ni = 0; ni < 4; ni++) {
                        const int nj = ni >> 1, sel = ni & 1;
                        mma16816(c[mi][ni], a[mi], b[nj][sel], b[nj][sel + 2]);
                    }
            }
        }
        __syncthreads();
    }

#pragma unroll
    for (int mi = 0; mi < 4; mi++)
#pragma unroll
        for (int h8 = 0; h8 < 2; h8++) {
            const int row = m0 + wm * 64 + mi * 16 + (lane >> 2) + h8 * 8;
#pragma unroll
            for (int ni = 0; ni < 4; ni++) {
                const int col = n0 + wn * 32 + ni * 8 + (lane & 3) * 2;
                epi(row, col, make_float2(c[mi][ni][h8 * 2], c[mi][ni][h8 * 2 + 1]));
            }
        }
}

// ---------------------------------------------------------------------------
// Pack / transpose kernels
// ---------------------------------------------------------------------------
__global__ void k_packx(const float* __restrict__ x){
    int i = blockIdx.x * 256 + threadIdx.x;
    float f = x[i];
    __half h = __float2half_rn(f);
    g_Xh[i] = h;
    g_Xl[i] = __float2half_rn(f - __half2float(h));
}

__global__ void k_packw(const float* __restrict__ W, __half* __restrict__ oh,
                        __half* __restrict__ ol, int R, int C){
    __shared__ float t[32][33];
    int c0 = blockIdx.x * 32, r0 = blockIdx.y * 32;
    int x = threadIdx.x, y = threadIdx.y;
#pragma unroll
    for (int i = 0; i < 32; i += 8) t[y + i][x] = W[(size_t)(r0 + y + i) * C + c0 + x];
    __syncthreads();
#pragma unroll
    for (int i = 0; i < 32; i += 8) {
        float wv = t[x][y + i];
        __half h = __float2half_rn(wv);
        size_t o = (size_t)(c0 + y + i) * R + r0 + x;
        oh[o] = h;
        ol[o] = __float2half_rn(wv - __half2float(h));
    }
}

__global__ void k_vt(){
    __shared__ __half t[32][33];
    int bh = blockIdx.z;
    int d0 = blockIdx.x * 32, t0 = blockIdx.y * 32;
    int x = threadIdx.x, y = threadIdx.y;
    const __half* src = g_Vh + (size_t)bh * TT * DD;
    __half* dst = g_VT + (size_t)bh * DD * TT;
#pragma unroll
    for (int i = 0; i < 32; i += 8) t[y + i][x] = src[(size_t)(t0 + y + i) * DD + d0 + x];
    __syncthreads();
#pragma unroll
    for (int i = 0; i < 32; i += 8) dst[(size_t)(d0 + y + i) * TT + t0 + x] = t[x][y + i];
}

// ---------------------------------------------------------------------------
// Projection kernels
// ---------------------------------------------------------------------------
__global__ __launch_bounds__(256, 2) void k_qkv(){
    const int z = blockIdx.z;
    const int m0 = blockIdx.y * 128, n0 = blockIdx.x * 128;
    const __half* Bh_ = g_WTh + (size_t)z * NNQKV * DD;
    const __half* Bl_ = g_WTl + (size_t)z * NNQKV * DD;
    gemm_core<true>(g_Xh, g_Xl, DD, Bh_, Bl_, DD, m0, n0, DD,
        [&](int row, int col, float2 v){
            int b = row >> 10, t = row & 1023, h = col >> 8, d = col & 255;
            size_t o = ((size_t)(b * HH + h) * TT + t) * DD + d;
            if (z == 2) {
                *reinterpret_cast<__half2*>(&g_Vh[o]) =
                    __halves2half2(__float2half_rn(v.x), __float2half_rn(v.y));
            } else {
                __half* Hh = (z == 0) ? g_Qh : g_Kh;
                *reinterpret_cast<__half2*>(&Hh[o]) =
                    __halves2half2(__float2half_rn(v.x * 0.25f), __float2half_rn(v.y * 0.25f));
            }
        });
}

__global__ __launch_bounds__(256, 2) void k_out(const float* __restrict__ bu,
                                                float* __restrict__ Cout){
    const int m0 = blockIdx.y * 128, n0 = blockIdx.x * 128;
    gemm_core<true>(g_Oh, g_Ol, NNQKV, g_WuTh, g_WuTl, NNQKV, m0, n0, NNQKV,
        [&](int row, int col, float2 v){
            float2 b2 = *reinterpret_cast<const float2*>(bu + col);
            *reinterpret_cast<float2*>(Cout + (size_t)row * DD + col) =
                make_float2(v.x + b2.x, v.y + b2.y);
        });
}

// ---------------------------------------------------------------------------
// Fused flash attention: per CTA = (bh, 128 q-rows), warp = 16 rows x full s.
// Loop over 16 key-tiles of 64: S = Q@K^T (mma), exp in regs, P-frag reuse
// (C-frag == A-frag layout), O += P@V^T, row sums in-warp. Normalize at end,
// write O as (hi,lo) halves. SMEM: Q 66K + K 2x33K + VT 2x36K = 204 KB.
// ---------------------------------------------------------------------------
#define QSTR 528            // 256 halves + 16B pad (odd multiple of 16)
#define VSTR 144            // 64 halves + 16B pad
#define KS_OFF   (128*QSTR)             // 67584
#define VS_OFF   (KS_OFF + 2*64*QSTR)   // 135168
#define SM_ATT   (VS_OFF + 2*256*VSTR)  // 208896

__global__ __launch_bounds__(256) void k_attn(){
    extern __shared__ __half smbuf[];
    const uint32_t smb = smem_u32(smbuf);
    const int bh = blockIdx.y;
    const int q0 = blockIdx.x * 128;
    const int tid = threadIdx.x, lane = tid & 31, w = tid >> 5;

    const __half* Qg = g_Qh + (size_t)bh * TT * DD + (size_t)q0 * DD;
    const __half* Kg = g_Kh + (size_t)bh * TT * DD;
    const __half* Vg = g_VT + (size_t)bh * DD * TT;

    // Q load: 128 rows x 512B
#pragma unroll
    for (int p = 0; p < 16; p++) {
        int i = p * 256 + tid, r = i >> 5, ch = i & 31;
        cp_async16(smb + r * QSTR + ch * 16, Qg + r * DD + ch * 8);
    }
    auto loadKV = [&](int it, int buf){
        const __half* Kt = Kg + (size_t)it * 64 * DD;
#pragma unroll
        for (int p = 0; p < 8; p++) {
            int i = p * 256 + tid, r = i >> 5, ch = i & 31;
            cp_async16(smb + KS_OFF + buf * (64*QSTR) + r * QSTR + ch * 16,
                       Kt + r * DD + ch * 8);
        }
#pragma unroll
        for (int p = 0; p < 8; p++) {
            int i = p * 256 + tid, r = i >> 3, ch = i & 7;
            cp_async16(smb + VS_OFF + buf * (256*VSTR) + r * VSTR + ch * 16,
                       Vg + (size_t)r * TT + it * 64 + ch * 8);
        }
        cp_commit();
    };
    loadKV(0, 0);   // group 0 = Q + KV0

    float o[32][4];
#pragma unroll
    for (int j = 0; j < 32; j++)
#pragma unroll
        for (int q = 0; q < 4; q++) o[j][q] = 0.f;
    float rs0 = 0.f, rs1 = 0.f;

    const uint32_t lA = (uint32_t)(lane & 15) * QSTR + (uint32_t)(lane >> 4) * 16;
    const uint32_t aB = smb + (uint32_t)(16 * w) * QSTR + lA;
    const uint32_t vL = (uint32_t)(lane & 15) * VSTR + (uint32_t)(lane >> 4) * 16;

    for (int it = 0; it < 16; it++) {
        cp_wait<0>();
        __syncthreads();
        if (it + 1 < 16) loadKV(it + 1, (it + 1) & 1);
        const int buf = it & 1;
        const uint32_t kB = smb + KS_OFF + buf * (64*QSTR) + lA;

        // --- S = Q @ K^T : 16 rows x 64 cols per warp ---
        float c[8][4];
#pragma unroll
        for (int j = 0; j < 8; j++)
#pragma unroll
            for (int q = 0; q < 4; q++) c[j][q] = 0.f;
#pragma unroll
        for (int ks = 0; ks < 16; ks++) {
            uint32_t a[4]; ldsm4(a, aB + ks * 32);
#pragma unroll
            for (int g = 0; g < 4; g++) {
                uint32_t b[4]; ldsm4(b, kB + g * (16*QSTR) + ks * 32);
                mma16816(c[2*g],     a, b[0], b[2]);
                mma16816(c[2*g + 1], a, b[1], b[3]);
            }
        }

        // --- exp -> P frags (C-frag == A-frag layout), row sums from rounded P ---
        uint32_t p[4][4];
#pragma unroll
        for (int j = 0; j < 8; j++)
#pragma unroll
            for (int q = 0; q < 4; q++) c[j][q] = __expf(c[j][q]);
#pragma unroll
        for (int ks2 = 0; ks2 < 4; ks2++) {
            const int j0 = 2 * ks2, j1 = j0 + 1;
            __half2 h00 = __floats2half2_rn(c[j0][0], c[j0][1]);
            __half2 h01 = __floats2half2_rn(c[j0][2], c[j0][3]);
            __half2 h10 = __floats2half2_rn(c[j1][0], c[j1][1]);
            __half2 h11 = __floats2half2_rn(c[j1][2], c[j1][3]);
            p[ks2][0] = *reinterpret_cast<uint32_t*>(&h00);
            p[ks2][1] = *reinterpret_cast<uint32_t*>(&h01);
            p[ks2][2] = *reinterpret_cast<uint32_t*>(&h10);
            p[ks2][3] = *reinterpret_cast<uint32_t*>(&h11);
            float2 f;
            f = __half22float2(h00); rs0 += f.x + f.y;
            f = __half22float2(h10); rs0 += f.x + f.y;
            f = __half22float2(h01); rs1 += f.x + f.y;
            f = __half22float2(h11); rs1 += f.x + f.y;
        }

        // --- O += P @ V^T : contraction over s=64, n = d = 256 ---
        const uint32_t vB = smb + VS_OFF + buf * (256*VSTR) + vL;
#pragma unroll
        for (int ks2 = 0; ks2 < 4; ks2++) {
#pragma unroll
            for (int dg = 0; dg < 16; dg++) {
                uint32_t b[4]; ldsm4(b, vB + dg * (16*VSTR) + ks2 * 32);
                mma16816(o[2*dg],     p[ks2], b[0], b[2]);
                mma16816(o[2*dg + 1], p[ks2], b[1], b[3]);
            }
        }
    }

    // --- finalize: reduce row sums over lane&3 group, normalize, write hi/lo ---
    rs0 += __shfl_xor_sync(0xffffffffu, rs0, 1);
    rs0 += __shfl_xor_sync(0xffffffffu, rs0, 2);
    rs1 += __shfl_xor_sync(0xffffffffu, rs1, 1);
    rs1 += __shfl_xor_sync(0xffffffffu, rs1, 2);
    const float inv0 = 1.0f / rs0, inv1 = 1.0f / rs1;

    const int b = bh >> 3, h = bh & 7;
    const int r0 = q0 + 16 * w + (lane >> 2), r1 = r0 + 8;
    __half* Oh0 = g_Oh + (size_t)(b * TT + r0) * NNQKV + h * DD;
    __half* Oh1 = g_Oh + (size_t)(b * TT + r1) * NNQKV + h * DD;
    __half* Ol0 = g_Ol + (size_t)(b * TT + r0) * NNQKV + h * DD;
    __half* Ol1 = g_Ol + (size_t)(b * TT + r1) * NNQKV + h * DD;
#pragma unroll
    for (int j = 0; j < 32; j++) {
        const int col = j * 8 + (lane & 3) * 2;
        float x0 = o[j][0] * inv0, y0 = o[j][1] * inv0;
        float x1 = o[j][2] * inv1, y1 = o[j][3] * inv1;
        __half hx0 = __float2half_rn(x0), hy0 = __float2half_rn(y0);
        __half hx1 = __float2half_rn(x1), hy1 = __float2half_rn(y1);
        *reinterpret_cast<__half2*>(Oh0 + col) = __halves2half2(hx0, hy0);
        *reinterpret_cast<__half2*>(Oh1 + col) = __halves2half2(hx1, hy1);
        *reinterpret_cast<__half2*>(Ol0 + col) = __halves2half2(
            __float2half_rn(x0 - __half2float(hx0)), __float2half_rn(y0 - __half2float(hy0)));
        *reinterpret_cast<__half2*>(Ol1 + col) = __halves2half2(
            __float2half_rn(x1 - __half2float(hx1)), __float2half_rn(y1 - __half2float(hy1)));
    }
}

// ---------------------------------------------------------------------------
extern "C" void kernel_launch(void* const* d_in, const int* in_sizes, int n_in,
                              void* d_out, int out_size)
{
    const float* x  = (const float*)d_in[0];
    const float* Wq = (const float*)d_in[1];
    const float* Wk = (const float*)d_in[2];
    const float* Wv = (const float*)d_in[3];
    const float* Wu = (const float*)d_in[4];
    const float* bu = (const float*)d_in[5];
    float* out = (float*)d_out;

    cudaFuncSetAttribute(k_qkv,  cudaFuncAttributeMaxDynamicSharedMemorySize, SM3);
    cudaFuncSetAttribute(k_out,  cudaFuncAttributeMaxDynamicSharedMemorySize, SM3);
    cudaFuncSetAttribute(k_attn, cudaFuncAttributeMaxDynamicSharedMemorySize, SM_ATT);

    __half *pWTh, *pWTl, *pWuTh, *pWuTl;
    cudaGetSymbolAddress((void**)&pWTh,  g_WTh);
    cudaGetSymbolAddress((void**)&pWTl,  g_WTl);
    cudaGetSymbolAddress((void**)&pWuTh, g_WuTh);
    cudaGetSymbolAddress((void**)&pWuTl, g_WuTl);

    dim3 tb(32, 8);
    k_packx<<<MMALL * DD / 256, 256>>>(x);
    k_packw<<<dim3(NNQKV / 32, DD / 32), tb>>>(Wq, pWTh,                  pWTl,                  DD, NNQKV);
    k_packw<<<dim3(NNQKV / 32, DD / 32), tb>>>(Wk, pWTh + NNQKV * DD,     pWTl + NNQKV * DD,     DD, NNQKV);
    k_packw<<<dim3(NNQKV / 32, DD / 32), tb>>>(Wv, pWTh + 2 * NNQKV * DD, pWTl + 2 * NNQKV * DD, DD, NNQKV);
    k_packw<<<dim3(DD / 32, NNQKV / 32), tb>>>(Wu, pWuTh,                 pWuTl,                 NNQKV, DD);

    k_qkv <<<dim3(NNQKV / 128, MMALL / 128, 3), 256, SM3>>>();
    k_vt  <<<dim3(DD / 32, TT / 32, BH), tb>>>();
    k_attn<<<dim3(TT / 128, BH), 256, SM_ATT>>>();
    k_out <<<dim3(DD / 128, MMALL / 128, 1), 256, SM3>>>(bu, out);
}

// round 14
// speedup vs baseline: 4.7412x; 1.2880x over previous
#include <cuda_runtime.h>
#include <cuda_fp16.h>
#include <cstdint>

#define BB   8
#define TT   1024
#define DD   256
#define HH   8
#define BH   (BB*HH)      // 64
#define MMALL (BB*TT)     // 8192
#define NNQKV (HH*DD)     // 2048

// ---------------------------------------------------------------------------
// Device scratch (no allocations allowed). 16B-aligned for half2/cp.async.
// ---------------------------------------------------------------------------
__device__ __align__(16) __half g_Xh [MMALL*DD];
__device__ __align__(16) __half g_WTh[3*NNQKV*DD];      // [n=2048][k=256] per z
__device__ __align__(16) __half g_WuTh[DD*NNQKV];       // [n=256][k=2048]
__device__ __align__(16) __half g_WuTl[DD*NNQKV];
__device__ __align__(16) __half g_Qh [BH*TT*DD];        // [bh][t][d], x0.25
__device__ __align__(16) __half g_Kh [BH*TT*DD];        // [bh][t][d], x0.25
__device__ __align__(16) __half g_VT [BH*DD*TT];        // [bh][d][t]
__device__ __align__(16) __half g_Oh [MMALL*NNQKV];     // [b*t][h*d]
__device__ __align__(16) __half g_Ol [MMALL*NNQKV];

// ---------------------------------------------------------------------------
// PTX helpers (sm_80-era instructions only; valid at sm_103 base target)
// ---------------------------------------------------------------------------
__device__ __forceinline__ uint32_t smem_u32(const void* p){
    uint32_t a;
    asm("{ .reg .u64 t; cvta.to.shared.u64 t, %1; cvt.u32.u64 %0, t; }" : "=r"(a) : "l"(p));
    return a;
}
__device__ __forceinline__ void cp_async16(uint32_t dst, const __half* src){
    uint64_t g; asm("cvta.to.global.u64 %0, %1;" : "=l"(g) : "l"(src));
    asm volatile("cp.async.ca.shared.global [%0], [%1], 16;" :: "r"(dst), "l"(g));
}
__device__ __forceinline__ void cp_commit(){ asm volatile("cp.async.commit_group;" ::: "memory"); }
template<int N> __device__ __forceinline__ void cp_wait(){
    asm volatile("cp.async.wait_group %0;" :: "n"(N) : "memory");
}
__device__ __forceinline__ void ldsm4(uint32_t r[4], uint32_t addr){
    asm volatile("ldmatrix.sync.aligned.m8n8.x4.shared.b16 {%0,%1,%2,%3}, [%4];"
        : "=r"(r[0]), "=r"(r[1]), "=r"(r[2]), "=r"(r[3]) : "r"(addr));
}
__device__ __forceinline__ void mma16816(float c[4], const uint32_t a[4],
                                         uint32_t b0, uint32_t b1){
    asm volatile("mma.sync.aligned.m16n8k16.row.col.f32.f16.f16.f32 "
        "{%0,%1,%2,%3},{%4,%5,%6,%7},{%8,%9},{%0,%1,%2,%3};"
        : "+f"(c[0]), "+f"(c[1]), "+f"(c[2]), "+f"(c[3])
        : "r"(a[0]), "r"(a[1]), "r"(a[2]), "r"(a[3]), "r"(b0), "r"(b1));
}

// ---------------------------------------------------------------------------
// GEMM core (projections): C[128,128] = A[128xK] @ B[128xK]^T.
// SPLIT: (hi,lo) pairs; AhBh + AhBl + AlBh, fp32 acc. 8 warps (2x4, 64x32).
// BK=32, 2-stage cp.async. Row stride 80B -> conflict-free + 2 CTAs/SM.
// ---------------------------------------------------------------------------
#define ROWB     80
#define TILE_B   (128*ROWB)         // 10240
#define SM3      (2*4*TILE_B)       // 81920
#define SM1      (2*2*TILE_B)       // 40960

template<bool SPLIT, class Epi>
__device__ __forceinline__ void gemm_core(
    const __half* __restrict__ Ah, const __half* __restrict__ Al, int lda,
    const __half* __restrict__ Bh, const __half* __restrict__ Bl, int ldb,
    int m0, int n0, int K, Epi&& epi)
{
    constexpr int NT = SPLIT ? 4 : 2;
    extern __shared__ __half smbuf[];
    const uint32_t smb = smem_u32(smbuf);
    const int tid  = threadIdx.x;
    const int lane = tid & 31, w = tid >> 5;

    const int lrow = lane + 32 * (w & 3);
    const int lch0 = (w >> 2) * 2;

    float c[4][4][4];
#pragma unroll
    for (int i = 0; i < 4; i++)
#pragma unroll
        for (int j = 0; j < 4; j++)
#pragma unroll
            for (int q = 0; q < 4; q++) c[i][j][q] = 0.f;

    auto ldst = [&](int t, const __half* src, int ld, int rowbase, int k0, int buf){
        const __half* s = src + (size_t)(rowbase + lrow) * ld + k0 + lch0 * 8;
        uint32_t d = smb + (buf * NT + t) * TILE_B + lrow * ROWB + lch0 * 16;
        cp_async16(d,      s);
        cp_async16(d + 16, s + 8);
    };
    auto load_stage = [&](int k0, int buf){
        ldst(0, Ah, lda, m0, k0, buf);
        ldst(1, Bh, ldb, n0, k0, buf);
        if (SPLIT) { ldst(2, Al, lda, m0, k0, buf); ldst(3, Bl, ldb, n0, k0, buf); }
        cp_commit();
    };

    const int wm = w & 1, wn = w >> 1;
    const uint32_t lA = (uint32_t)(lane & 15) * ROWB + (uint32_t)(lane >> 4) * 16;
    const uint32_t aOff = (uint32_t)(wm * 64) * ROWB + lA;
    const uint32_t bOff = (uint32_t)(wn * 32) * ROWB + lA;

    load_stage(0, 0);
    const int NST = K >> 5;
    for (int s = 0; s < NST; s++) {
        if (s + 1 < NST) { load_stage((s + 1) << 5, (s + 1) & 1); cp_wait<1>(); }
        else             { cp_wait<0>(); }
        __syncthreads();

        const int buf = s & 1;
        const uint32_t aHiB = smb + (buf * NT + 0) * TILE_B + aOff;
        const uint32_t bHiB = smb + (buf * NT + 1) * TILE_B + bOff;
        const uint32_t aLoB = SPLIT ? smb + (buf * NT + 2) * TILE_B + aOff : 0;
        const uint32_t bLoB = SPLIT ? smb + (buf * NT + 3) * TILE_B + bOff : 0;

#pragma unroll
        for (int k16 = 0; k16 < 2; k16++) {
            const uint32_t kb = k16 * 32;
            const int NP = SPLIT ? 3 : 1;
#pragma unroll
            for (int p = 0; p < NP; p++) {
                const uint32_t aB = (p == 2) ? aLoB : aHiB;
                const uint32_t bB = (p == 1) ? bLoB : bHiB;
                uint32_t a[4][4];
#pragma unroll
                for (int mi = 0; mi < 4; mi++) ldsm4(a[mi], aB + mi * (16*ROWB) + kb);
                uint32_t b[2][4];
#pragma unroll
                for (int nj = 0; nj < 2; nj++) ldsm4(b[nj], bB + nj * (16*ROWB) + kb);
#pragma unroll
                for (int mi = 0; mi < 4; mi++)
#pragma unroll
                    for (int ni = 0; ni < 4; ni++) {
                        const int nj = ni >> 1, sel = ni & 1;
                        mma16816(c[mi][ni], a[mi], b[nj][sel], b[nj][sel + 2]);
                    }
            }
        }
        __syncthreads();
    }

#pragma unroll
    for (int mi = 0; mi < 4; mi++)
#pragma unroll
        for (int h8 = 0; h8 < 2; h8++) {
            const int row = m0 + wm * 64 + mi * 16 + (lane >> 2) + h8 * 8;
#pragma unroll
            for (int ni = 0; ni < 4; ni++) {
                const int col = n0 + wn * 32 + ni * 8 + (lane & 3) * 2;
                epi(row, col, make_float2(c[mi][ni][h8 * 2], c[mi][ni][h8 * 2 + 1]));
            }
        }
}

// ---------------------------------------------------------------------------
// Pack kernels
// ---------------------------------------------------------------------------
__global__ void k_packx(const float* __restrict__ x){
    int i = blockIdx.x * 256 + threadIdx.x;
    g_Xh[i] = __float2half_rn(x[i]);
}

// W[R][C] fp32 -> half [C][R]; lo written only if ol != nullptr
__global__ void k_packw(const float* __restrict__ W, __half* __restrict__ oh,
                        __half* __restrict__ ol, int R, int C){
    __shared__ float t[32][33];
    int c0 = blockIdx.x * 32, r0 = blockIdx.y * 32;
    int x = threadIdx.x, y = threadIdx.y;
#pragma unroll
    for (int i = 0; i < 32; i += 8) t[y + i][x] = W[(size_t)(r0 + y + i) * C + c0 + x];
    __syncthreads();
#pragma unroll
    for (int i = 0; i < 32; i += 8) {
        float wv = t[x][y + i];
        __half h = __float2half_rn(wv);
        size_t o = (size_t)(c0 + y + i) * R + r0 + x;
        oh[o] = h;
        if (ol) ol[o] = __float2half_rn(wv - __half2float(h));
    }
}

// ---------------------------------------------------------------------------
// Projection kernels
// ---------------------------------------------------------------------------
__global__ __launch_bounds__(256, 2) void k_qkv(){
    const int z = blockIdx.z;
    const int m0 = blockIdx.y * 128, n0 = blockIdx.x * 128;
    const __half* Bh_ = g_WTh + (size_t)z * NNQKV * DD;
    gemm_core<false>(g_Xh, nullptr, DD, Bh_, nullptr, DD, m0, n0, DD,
        [&](int row, int col, float2 v){
            int b = row >> 10, t = row & 1023, h = col >> 8, d = col & 255;
            if (z == 2) {
                // write V transposed: [bh][d][t]
                __half* dst = g_VT + ((size_t)(b * HH + h) * DD + d) * TT + t;
                dst[0]  = __float2half_rn(v.x);
                dst[TT] = __float2half_rn(v.y);
            } else {
                size_t o = ((size_t)(b * HH + h) * TT + t) * DD + d;
                __half* Hh = (z == 0) ? g_Qh : g_Kh;
                *reinterpret_cast<__half2*>(&Hh[o]) =
                    __halves2half2(__float2half_rn(v.x * 0.25f), __float2half_rn(v.y * 0.25f));
            }
        });
}

__global__ __launch_bounds__(256, 2) void k_out(const float* __restrict__ bu,
                                                float* __restrict__ Cout){
    const int m0 = blockIdx.y * 128, n0 = blockIdx.x * 128;
    gemm_core<true>(g_Oh, g_Ol, NNQKV, g_WuTh, g_WuTl, NNQKV, m0, n0, NNQKV,
        [&](int row, int col, float2 v){
            float2 b2 = *reinterpret_cast<const float2*>(bu + col);
            *reinterpret_cast<float2*>(Cout + (size_t)row * DD + col) =
                make_float2(v.x + b2.x, v.y + b2.y);
        });
}

// ---------------------------------------------------------------------------
// Fused flash attention: per CTA = (bh, 128 q-rows), warp = 16 rows x full s.
// Loop over 16 key-tiles of 64: S = Q@K^T (mma), exp in regs, P-frag reuse
// (C-frag == A-frag layout), O += P@V^T, row sums in-warp. Normalize at end,
// write O as (hi,lo) halves. SMEM: Q 66K + K 2x33K + VT 2x36K = 204 KB.
// ---------------------------------------------------------------------------
#define QSTR 528            // 256 halves + 16B pad (odd multiple of 16)
#define VSTR 144            // 64 halves + 16B pad
#define KS_OFF   (128*QSTR)             // 67584
#define VS_OFF   (KS_OFF + 2*64*QSTR)   // 135168
#define SM_ATT   (VS_OFF + 2*256*VSTR)  // 208896

__global__ __launch_bounds__(256) void k_attn(){
    extern __shared__ __half smbuf[];
    const uint32_t smb = smem_u32(smbuf);
    const int bh = blockIdx.y;
    const int q0 = blockIdx.x * 128;
    const int tid = threadIdx.x, lane = tid & 31, w = tid >> 5;

    const __half* Qg = g_Qh + (size_t)bh * TT * DD + (size_t)q0 * DD;
    const __half* Kg = g_Kh + (size_t)bh * TT * DD;
    const __half* Vg = g_VT + (size_t)bh * DD * TT;

    // Q load: 128 rows x 512B
#pragma unroll
    for (int p = 0; p < 16; p++) {
        int i = p * 256 + tid, r = i >> 5, ch = i & 31;
        cp_async16(smb + r * QSTR + ch * 16, Qg + r * DD + ch * 8);
    }
    auto loadKV = [&](int it, int buf){
        const __half* Kt = Kg + (size_t)it * 64 * DD;
#pragma unroll
        for (int p = 0; p < 8; p++) {
            int i = p * 256 + tid, r = i >> 5, ch = i & 31;
            cp_async16(smb + KS_OFF + buf * (64*QSTR) + r * QSTR + ch * 16,
                       Kt + r * DD + ch * 8);
        }
#pragma unroll
        for (int p = 0; p < 8; p++) {
            int i = p * 256 + tid, r = i >> 3, ch = i & 7;
            cp_async16(smb + VS_OFF + buf * (256*VSTR) + r * VSTR + ch * 16,
                       Vg + (size_t)r * TT + it * 64 + ch * 8);
        }
        cp_commit();
    };
    loadKV(0, 0);

    float o[32][4];
#pragma unroll
    for (int j = 0; j < 32; j++)
#pragma unroll
        for (int q = 0; q < 4; q++) o[j][q] = 0.f;
    float rs0 = 0.f, rs1 = 0.f;

    const uint32_t lA = (uint32_t)(lane & 15) * QSTR + (uint32_t)(lane >> 4) * 16;
    const uint32_t aB = smb + (uint32_t)(16 * w) * QSTR + lA;
    const uint32_t vL = (uint32_t)(lane & 15) * VSTR + (uint32_t)(lane >> 4) * 16;

    for (int it = 0; it < 16; it++) {
        cp_wait<0>();
        __syncthreads();
        if (it + 1 < 16) loadKV(it + 1, (it + 1) & 1);
        const int buf = it & 1;
        const uint32_t kB = smb + KS_OFF + buf * (64*QSTR) + lA;

        // --- S = Q @ K^T : 16 rows x 64 cols per warp ---
        float c[8][4];
#pragma unroll
        for (int j = 0; j < 8; j++)
#pragma unroll
            for (int q = 0; q < 4; q++) c[j][q] = 0.f;
#pragma unroll
        for (int ks = 0; ks < 16; ks++) {
            uint32_t a[4]; ldsm4(a, aB + ks * 32);
#pragma unroll
            for (int g = 0; g < 4; g++) {
                uint32_t b[4]; ldsm4(b, kB + g * (16*QSTR) + ks * 32);
                mma16816(c[2*g],     a, b[0], b[2]);
                mma16816(c[2*g + 1], a, b[1], b[3]);
            }
        }

        // --- exp -> P frags (C-frag == A-frag layout), row sums from rounded P ---
        uint32_t p[4][4];
#pragma unroll
        for (int j = 0; j < 8; j++)
#pragma unroll
            for (int q = 0; q < 4; q++) c[j][q] = __expf(c[j][q]);
#pragma unroll
        for (int ks2 = 0; ks2 < 4; ks2++) {
            const int j0 = 2 * ks2, j1 = j0 + 1;
            __half2 h00 = __floats2half2_rn(c[j0][0], c[j0][1]);
            __half2 h01 = __floats2half2_rn(c[j0][2], c[j0][3]);
            __half2 h10 = __floats2half2_rn(c[j1][0], c[j1][1]);
            __half2 h11 = __floats2half2_rn(c[j1][2], c[j1][3]);
            p[ks2][0] = *reinterpret_cast<uint32_t*>(&h00);
            p[ks2][1] = *reinterpret_cast<uint32_t*>(&h01);
            p[ks2][2] = *reinterpret_cast<uint32_t*>(&h10);
            p[ks2][3] = *reinterpret_cast<uint32_t*>(&h11);
            float2 f;
            f = __half22float2(h00); rs0 += f.x + f.y;
            f = __half22float2(h10); rs0 += f.x + f.y;
            f = __half22float2(h01); rs1 += f.x + f.y;
            f = __half22float2(h11); rs1 += f.x + f.y;
        }

        // --- O += P @ V^T : contraction over s=64, n = d = 256 ---
        const uint32_t vB = smb + VS_OFF + buf * (256*VSTR) + vL;
#pragma unroll
        for (int ks2 = 0; ks2 < 4; ks2++) {
#pragma unroll
            for (int dg = 0; dg < 16; dg++) {
                uint32_t b[4]; ldsm4(b, vB + dg * (16*VSTR) + ks2 * 32);
                mma16816(o[2*dg],     p[ks2], b[0], b[2]);
                mma16816(o[2*dg + 1], p[ks2], b[1], b[3]);
            }
        }
    }

    // --- finalize ---
    rs0 += __shfl_xor_sync(0xffffffffu, rs0, 1);
    rs0 += __shfl_xor_sync(0xffffffffu, rs0, 2);
    rs1 += __shfl_xor_sync(0xffffffffu, rs1, 1);
    rs1 += __shfl_xor_sync(0xffffffffu, rs1, 2);
    const float inv0 = 1.0f / rs0, inv1 = 1.0f / rs1;

    const int b = bh >> 3, h = bh & 7;
    const int r0 = q0 + 16 * w + (lane >> 2), r1 = r0 + 8;
    __half* Oh0 = g_Oh + (size_t)(b * TT + r0) * NNQKV + h * DD;
    __half* Oh1 = g_Oh + (size_t)(b * TT + r1) * NNQKV + h * DD;
    __half* Ol0 = g_Ol + (size_t)(b * TT + r0) * NNQKV + h * DD;
    __half* Ol1 = g_Ol + (size_t)(b * TT + r1) * NNQKV + h * DD;
#pragma unroll
    for (int j = 0; j < 32; j++) {
        const int col = j * 8 + (lane & 3) * 2;
        float x0 = o[j][0] * inv0, y0 = o[j][1] * inv0;
        float x1 = o[j][2] * inv1, y1 = o[j][3] * inv1;
        __half hx0 = __float2half_rn(x0), hy0 = __float2half_rn(y0);
        __half hx1 = __float2half_rn(x1), hy1 = __float2half_rn(y1);
        *reinterpret_cast<__half2*>(Oh0 + col) = __halves2half2(hx0, hy0);
        *reinterpret_cast<__half2*>(Oh1 + col) = __halves2half2(hx1, hy1);
        *reinterpret_cast<__half2*>(Ol0 + col) = __halves2half2(
            __float2half_rn(x0 - __half2float(hx0)), __float2half_rn(y0 - __half2float(hy0)));
        *reinterpret_cast<__half2*>(Ol1 + col) = __halves2half2(
            __float2half_rn(x1 - __half2float(hx1)), __float2half_rn(y1 - __half2float(hy1)));
    }
}

// ---------------------------------------------------------------------------
extern "C" void kernel_launch(void* const* d_in, const int* in_sizes, int n_in,
                              void* d_out, int out_size)
{
    const float* x  = (const float*)d_in[0];
    const float* Wq = (const float*)d_in[1];
    const float* Wk = (const float*)d_in[2];
    const float* Wv = (const float*)d_in[3];
    const float* Wu = (const float*)d_in[4];
    const float* bu = (const float*)d_in[5];
    float* out = (float*)d_out;

    cudaFuncSetAttribute(k_qkv,  cudaFuncAttributeMaxDynamicSharedMemorySize, SM1);
    cudaFuncSetAttribute(k_out,  cudaFuncAttributeMaxDynamicSharedMemorySize, SM3);
    cudaFuncSetAttribute(k_attn, cudaFuncAttributeMaxDynamicSharedMemorySize, SM_ATT);

    __half *pWTh, *pWuTh, *pWuTl;
    cudaGetSymbolAddress((void**)&pWTh,  g_WTh);
    cudaGetSymbolAddress((void**)&pWuTh, g_WuTh);
    cudaGetSymbolAddress((void**)&pWuTl, g_WuTl);

    dim3 tb(32, 8);
    k_packx<<<MMALL * DD / 256, 256>>>(x);
    k_packw<<<dim3(NNQKV / 32, DD / 32), tb>>>(Wq, pWTh,                  nullptr, DD, NNQKV);
    k_packw<<<dim3(NNQKV / 32, DD / 32), tb>>>(Wk, pWTh + NNQKV * DD,     nullptr, DD, NNQKV);
    k_packw<<<dim3(NNQKV / 32, DD / 32), tb>>>(Wv, pWTh + 2 * NNQKV * DD, nullptr, DD, NNQKV);
    k_packw<<<dim3(DD / 32, NNQKV / 32), tb>>>(Wu, pWuTh,                 pWuTl,   NNQKV, DD);

    k_qkv <<<dim3(NNQKV / 128, MMALL / 128, 3), 256, SM1>>>();
    k_attn<<<dim3(TT / 128, BH), 256, SM_ATT>>>();
    k_out <<<dim3(DD / 128, MMALL / 128, 1), 256, SM3>>>(bu, out);
}

// round 15
// speedup vs baseline: 5.4060x; 1.1402x over previous
#include <cuda_runtime.h>
#include <cuda_fp16.h>
#include <cstdint>

#define BB   8
#define TT   1024
#define DD   256
#define HH   8
#define BH   (BB*HH)      // 64
#define MMALL (BB*TT)     // 8192
#define NNQKV (HH*DD)     // 2048

// ---------------------------------------------------------------------------
// Device scratch (no allocations allowed). 16B-aligned for half2/cp.async.
// ---------------------------------------------------------------------------
__device__ __align__(16) __half g_Xh [MMALL*DD];
__device__ __align__(16) __half g_WTh[3*NNQKV*DD];      // [n=2048][k=256] per z
__device__ __align__(16) __half g_WuTh[DD*NNQKV];       // [n=256][k=2048]
__device__ __align__(16) __half g_Qh [BH*TT*DD];        // [bh][t][d], x0.25
__device__ __align__(16) __half g_Kh [BH*TT*DD];        // [bh][t][d], x0.25
__device__ __align__(16) __half g_VT [BH*DD*TT];        // [bh][d][t]
__device__ __align__(16) __half g_Oh [MMALL*NNQKV];     // [b*t][h*d]

// ---------------------------------------------------------------------------
// PTX helpers (sm_80-era instructions only; valid at sm_103 base target)
// ---------------------------------------------------------------------------
__device__ __forceinline__ uint32_t smem_u32(const void* p){
    uint32_t a;
    asm("{ .reg .u64 t; cvta.to.shared.u64 t, %1; cvt.u32.u64 %0, t; }" : "=r"(a) : "l"(p));
    return a;
}
__device__ __forceinline__ void cp_async16(uint32_t dst, const __half* src){
    uint64_t g; asm("cvta.to.global.u64 %0, %1;" : "=l"(g) : "l"(src));
    asm volatile("cp.async.ca.shared.global [%0], [%1], 16;" :: "r"(dst), "l"(g));
}
__device__ __forceinline__ void cp_commit(){ asm volatile("cp.async.commit_group;" ::: "memory"); }
template<int N> __device__ __forceinline__ void cp_wait(){
    asm volatile("cp.async.wait_group %0;" :: "n"(N) : "memory");
}
__device__ __forceinline__ void ldsm4(uint32_t r[4], uint32_t addr){
    asm volatile("ldmatrix.sync.aligned.m8n8.x4.shared.b16 {%0,%1,%2,%3}, [%4];"
        : "=r"(r[0]), "=r"(r[1]), "=r"(r[2]), "=r"(r[3]) : "r"(addr));
}
__device__ __forceinline__ void mma16816(float c[4], const uint32_t a[4],
                                         uint32_t b0, uint32_t b1){
    asm volatile("mma.sync.aligned.m16n8k16.row.col.f32.f16.f16.f32 "
        "{%0,%1,%2,%3},{%4,%5,%6,%7},{%8,%9},{%0,%1,%2,%3};"
        : "+f"(c[0]), "+f"(c[1]), "+f"(c[2]), "+f"(c[3])
        : "r"(a[0]), "r"(a[1]), "r"(a[2]), "r"(a[3]), "r"(b0), "r"(b1));
}

// ---------------------------------------------------------------------------
// GEMM core (projections): C[128,128] = A[128xK] @ B[128xK]^T.
// SPLIT: (hi,lo) pairs; AhBh + AhBl + AlBh, fp32 acc. 8 warps (2x4, 64x32).
// BK=32, 2-stage cp.async. Row stride 80B -> conflict-free + 2 CTAs/SM.
// ---------------------------------------------------------------------------
#define ROWB     80
#define TILE_B   (128*ROWB)         // 10240
#define SM1      (2*2*TILE_B)       // 40960

template<bool SPLIT, class Epi>
__device__ __forceinline__ void gemm_core(
    const __half* __restrict__ Ah, const __half* __restrict__ Al, int lda,
    const __half* __restrict__ Bh, const __half* __restrict__ Bl, int ldb,
    int m0, int n0, int K, Epi&& epi)
{
    constexpr int NT = SPLIT ? 4 : 2;
    extern __shared__ __half smbuf[];
    const uint32_t smb = smem_u32(smbuf);
    const int tid  = threadIdx.x;
    const int lane = tid & 31, w = tid >> 5;

    const int lrow = lane + 32 * (w & 3);
    const int lch0 = (w >> 2) * 2;

    float c[4][4][4];
#pragma unroll
    for (int i = 0; i < 4; i++)
#pragma unroll
        for (int j = 0; j < 4; j++)
#pragma unroll
            for (int q = 0; q < 4; q++) c[i][j][q] = 0.f;

    auto ldst = [&](int t, const __half* src, int ld, int rowbase, int k0, int buf){
        const __half* s = src + (size_t)(rowbase + lrow) * ld + k0 + lch0 * 8;
        uint32_t d = smb + (buf * NT + t) * TILE_B + lrow * ROWB + lch0 * 16;
        cp_async16(d,      s);
        cp_async16(d + 16, s + 8);
    };
    auto load_stage = [&](int k0, int buf){
        ldst(0, Ah, lda, m0, k0, buf);
        ldst(1, Bh, ldb, n0, k0, buf);
        if (SPLIT) { ldst(2, Al, lda, m0, k0, buf); ldst(3, Bl, ldb, n0, k0, buf); }
        cp_commit();
    };

    const int wm = w & 1, wn = w >> 1;
    const uint32_t lA = (uint32_t)(lane & 15) * ROWB + (uint32_t)(lane >> 4) * 16;
    const uint32_t aOff = (uint32_t)(wm * 64) * ROWB + lA;
    const uint32_t bOff = (uint32_t)(wn * 32) * ROWB + lA;

    load_stage(0, 0);
    const int NST = K >> 5;
    for (int s = 0; s < NST; s++) {
        if (s + 1 < NST) { load_stage((s + 1) << 5, (s + 1) & 1); cp_wait<1>(); }
        else             { cp_wait<0>(); }
        __syncthreads();

        const int buf = s & 1;
        const uint32_t aHiB = smb + (buf * NT + 0) * TILE_B + aOff;
        const uint32_t bHiB = smb + (buf * NT + 1) * TILE_B + bOff;
        const uint32_t aLoB = SPLIT ? smb + (buf * NT + 2) * TILE_B + aOff : 0;
        const uint32_t bLoB = SPLIT ? smb + (buf * NT + 3) * TILE_B + bOff : 0;

#pragma unroll
        for (int k16 = 0; k16 < 2; k16++) {
            const uint32_t kb = k16 * 32;
            const int NP = SPLIT ? 3 : 1;
#pragma unroll
            for (int p = 0; p < NP; p++) {
                const uint32_t aB = (p == 2) ? aLoB : aHiB;
                const uint32_t bB = (p == 1) ? bLoB : bHiB;
                uint32_t a[4][4];
#pragma unroll
                for (int mi = 0; mi < 4; mi++) ldsm4(a[mi], aB + mi * (16*ROWB) + kb);
                uint32_t b[2][4];
#pragma unroll
                for (int nj = 0; nj < 2; nj++) ldsm4(b[nj], bB + nj * (16*ROWB) + kb);
#pragma unroll
                for (int mi = 0; mi < 4; mi++)
#pragma unroll
                    for (int ni = 0; ni < 4; ni++) {
                        const int nj = ni >> 1, sel = ni & 1;
                        mma16816(c[mi][ni], a[mi], b[nj][sel], b[nj][sel + 2]);
                    }
            }
        }
        __syncthreads();
    }

#pragma unroll
    for (int mi = 0; mi < 4; mi++)
#pragma unroll
        for (int h8 = 0; h8 < 2; h8++) {
            const int row = m0 + wm * 64 + mi * 16 + (lane >> 2) + h8 * 8;
#pragma unroll
            for (int ni = 0; ni < 4; ni++) {
                const int col = n0 + wn * 32 + ni * 8 + (lane & 3) * 2;
                epi(row, col, make_float2(c[mi][ni][h8 * 2], c[mi][ni][h8 * 2 + 1]));
            }
        }
}

// ---------------------------------------------------------------------------
// Pack kernels
// ---------------------------------------------------------------------------
__global__ void k_packx(const float* __restrict__ x){
    int i = blockIdx.x * 256 + threadIdx.x;
    g_Xh[i] = __float2half_rn(x[i]);
}

// W[R][C] fp32 -> half [C][R]
__global__ void k_packw(const float* __restrict__ W, __half* __restrict__ oh,
                        int R, int C){
    __shared__ float t[32][33];
    int c0 = blockIdx.x * 32, r0 = blockIdx.y * 32;
    int x = threadIdx.x, y = threadIdx.y;
#pragma unroll
    for (int i = 0; i < 32; i += 8) t[y + i][x] = W[(size_t)(r0 + y + i) * C + c0 + x];
    __syncthreads();
#pragma unroll
    for (int i = 0; i < 32; i += 8)
        oh[(size_t)(c0 + y + i) * R + r0 + x] = __float2half_rn(t[x][y + i]);
}

// ---------------------------------------------------------------------------
// Projection kernels
// ---------------------------------------------------------------------------
__global__ __launch_bounds__(256, 2) void k_qkv(){
    const int z = blockIdx.z;
    const int m0 = blockIdx.y * 128, n0 = blockIdx.x * 128;
    const __half* Bh_ = g_WTh + (size_t)z * NNQKV * DD;
    gemm_core<false>(g_Xh, nullptr, DD, Bh_, nullptr, DD, m0, n0, DD,
        [&](int row, int col, float2 v){
            int b = row >> 10, t = row & 1023, h = col >> 8, d = col & 255;
            if (z == 2) {
                // write V transposed: [bh][d][t]
                __half* dst = g_VT + ((size_t)(b * HH + h) * DD + d) * TT + t;
                dst[0]  = __float2half_rn(v.x);
                dst[TT] = __float2half_rn(v.y);
            } else {
                size_t o = ((size_t)(b * HH + h) * TT + t) * DD + d;
                __half* Hh = (z == 0) ? g_Qh : g_Kh;
                *reinterpret_cast<__half2*>(&Hh[o]) =
                    __halves2half2(__float2half_rn(v.x * 0.25f), __float2half_rn(v.y * 0.25f));
            }
        });
}

__global__ __launch_bounds__(256, 2) void k_out(const float* __restrict__ bu,
                                                float* __restrict__ Cout){
    const int m0 = blockIdx.y * 128, n0 = blockIdx.x * 128;
    gemm_core<false>(g_Oh, nullptr, NNQKV, g_WuTh, nullptr, NNQKV, m0, n0, NNQKV,
        [&](int row, int col, float2 v){
            float2 b2 = *reinterpret_cast<const float2*>(bu + col);
            *reinterpret_cast<float2*>(Cout + (size_t)row * DD + col) =
                make_float2(v.x + b2.x, v.y + b2.y);
        });
}

// ---------------------------------------------------------------------------
// Fused flash attention: per CTA = (bh, 128 q-rows), warp = 16 rows x full s.
// Loop over 16 key-tiles of 64: S = Q@K^T (mma), exp in regs, P-frag reuse
// (C-frag == A-frag layout), O += P@V^T, row sums in-warp. Normalize at end.
// SMEM: Q 66K + K 2x33K + VT 2x36K = 204 KB.
// ---------------------------------------------------------------------------
#define QSTR 528            // 256 halves + 16B pad (odd multiple of 16)
#define VSTR 144            // 64 halves + 16B pad
#define KS_OFF   (128*QSTR)             // 67584
#define VS_OFF   (KS_OFF + 2*64*QSTR)   // 135168
#define SM_ATT   (VS_OFF + 2*256*VSTR)  // 208896

__global__ __launch_bounds__(256) void k_attn(){
    extern __shared__ __half smbuf[];
    const uint32_t smb = smem_u32(smbuf);
    const int bh = blockIdx.y;
    const int q0 = blockIdx.x * 128;
    const int tid = threadIdx.x, lane = tid & 31, w = tid >> 5;

    const __half* Qg = g_Qh + (size_t)bh * TT * DD + (size_t)q0 * DD;
    const __half* Kg = g_Kh + (size_t)bh * TT * DD;
    const __half* Vg = g_VT + (size_t)bh * DD * TT;

    // Q load: 128 rows x 512B
#pragma unroll
    for (int p = 0; p < 16; p++) {
        int i = p * 256 + tid, r = i >> 5, ch = i & 31;
        cp_async16(smb + r * QSTR + ch * 16, Qg + r * DD + ch * 8);
    }
    auto loadKV = [&](int it, int buf){
        const __half* Kt = Kg + (size_t)it * 64 * DD;
#pragma unroll
        for (int p = 0; p < 8; p++) {
            int i = p * 256 + tid, r = i >> 5, ch = i & 31;
            cp_async16(smb + KS_OFF + buf * (64*QSTR) + r * QSTR + ch * 16,
                       Kt + r * DD + ch * 8);
        }
#pragma unroll
        for (int p = 0; p < 8; p++) {
            int i = p * 256 + tid, r = i >> 3, ch = i & 7;
            cp_async16(smb + VS_OFF + buf * (256*VSTR) + r * VSTR + ch * 16,
                       Vg + (size_t)r * TT + it * 64 + ch * 8);
        }
        cp_commit();
    };
    loadKV(0, 0);

    float o[32][4];
#pragma unroll
    for (int j = 0; j < 32; j++)
#pragma unroll
        for (int q = 0; q < 4; q++) o[j][q] = 0.f;
    float rs0 = 0.f, rs1 = 0.f;

    const uint32_t lA = (uint32_t)(lane & 15) * QSTR + (uint32_t)(lane >> 4) * 16;
    const uint32_t aB = smb + (uint32_t)(16 * w) * QSTR + lA;
    const uint32_t vL = (uint32_t)(lane & 15) * VSTR + (uint32_t)(lane >> 4) * 16;

    for (int it = 0; it < 16; it++) {
        cp_wait<0>();
        __syncthreads();
        if (it + 1 < 16) loadKV(it + 1, (it + 1) & 1);
        const int buf = it & 1;
        const uint32_t kB = smb + KS_OFF + buf * (64*QSTR) + lA;

        // --- S = Q @ K^T : 16 rows x 64 cols per warp ---
        float c[8][4];
#pragma unroll
        for (int j = 0; j < 8; j++)
#pragma unroll
            for (int q = 0; q < 4; q++) c[j][q] = 0.f;
#pragma unroll
        for (int ks = 0; ks < 16; ks++) {
            uint32_t a[4]; ldsm4(a, aB + ks * 32);
#pragma unroll
            for (int g = 0; g < 4; g++) {
                uint32_t b[4]; ldsm4(b, kB + g * (16*QSTR) + ks * 32);
                mma16816(c[2*g],     a, b[0], b[2]);
                mma16816(c[2*g + 1], a, b[1], b[3]);
            }
        }

        // --- exp -> P frags (C-frag == A-frag layout), row sums from rounded P ---
        uint32_t p[4][4];
#pragma unroll
        for (int j = 0; j < 8; j++)
#pragma unroll
            for (int q = 0; q < 4; q++) c[j][q] = __expf(c[j][q]);
#pragma unroll
        for (int ks2 = 0; ks2 < 4; ks2++) {
            const int j0 = 2 * ks2, j1 = j0 + 1;
            __half2 h00 = __floats2half2_rn(c[j0][0], c[j0][1]);
            __half2 h01 = __floats2half2_rn(c[j0][2], c[j0][3]);
            __half2 h10 = __floats2half2_rn(c[j1][0], c[j1][1]);
            __half2 h11 = __floats2half2_rn(c[j1][2], c[j1][3]);
            p[ks2][0] = *reinterpret_cast<uint32_t*>(&h00);
            p[ks2][1] = *reinterpret_cast<uint32_t*>(&h01);
            p[ks2][2] = *reinterpret_cast<uint32_t*>(&h10);
            p[ks2][3] = *reinterpret_cast<uint32_t*>(&h11);
            float2 f;
            f = __half22float2(h00); rs0 += f.x + f.y;
            f = __half22float2(h10); rs0 += f.x + f.y;
            f = __half22float2(h01); rs1 += f.x + f.y;
            f = __half22float2(h11); rs1 += f.x + f.y;
        }

        // --- O += P @ V^T : contraction over s=64, n = d = 256 ---
        const uint32_t vB = smb + VS_OFF + buf * (256*VSTR) + vL;
#pragma unroll
        for (int ks2 = 0; ks2 < 4; ks2++) {
#pragma unroll
            for (int dg = 0; dg < 16; dg++) {
                uint32_t b[4]; ldsm4(b, vB + dg * (16*VSTR) + ks2 * 32);
                mma16816(o[2*dg],     p[ks2], b[0], b[2]);
                mma16816(o[2*dg + 1], p[ks2], b[1], b[3]);
            }
        }
    }

    // --- finalize ---
    rs0 += __shfl_xor_sync(0xffffffffu, rs0, 1);
    rs0 += __shfl_xor_sync(0xffffffffu, rs0, 2);
    rs1 += __shfl_xor_sync(0xffffffffu, rs1, 1);
    rs1 += __shfl_xor_sync(0xffffffffu, rs1, 2);
    const float inv0 = 1.0f / rs0, inv1 = 1.0f / rs1;

    const int b = bh >> 3, h = bh & 7;
    const int r0 = q0 + 16 * w + (lane >> 2), r1 = r0 + 8;
    __half* Oh0 = g_Oh + (size_t)(b * TT + r0) * NNQKV + h * DD;
    __half* Oh1 = g_Oh + (size_t)(b * TT + r1) * NNQKV + h * DD;
#pragma unroll
    for (int j = 0; j < 32; j++) {
        const int col = j * 8 + (lane & 3) * 2;
        *reinterpret_cast<__half2*>(Oh0 + col) =
            __floats2half2_rn(o[j][0] * inv0, o[j][1] * inv0);
        *reinterpret_cast<__half2*>(Oh1 + col) =
            __floats2half2_rn(o[j][2] * inv1, o[j][3] * inv1);
    }
}

// ---------------------------------------------------------------------------
extern "C" void kernel_launch(void* const* d_in, const int* in_sizes, int n_in,
                              void* d_out, int out_size)
{
    const float* x  = (const float*)d_in[0];
    const float* Wq = (const float*)d_in[1];
    const float* Wk = (const float*)d_in[2];
    const float* Wv = (const float*)d_in[3];
    const float* Wu = (const float*)d_in[4];
    const float* bu = (const float*)d_in[5];
    float* out = (float*)d_out;

    cudaFuncSetAttribute(k_qkv,  cudaFuncAttributeMaxDynamicSharedMemorySize, SM1);
    cudaFuncSetAttribute(k_out,  cudaFuncAttributeMaxDynamicSharedMemorySize, SM1);
    cudaFuncSetAttribute(k_attn, cudaFuncAttributeMaxDynamicSharedMemorySize, SM_ATT);

    __half *pWTh, *pWuTh;
    cudaGetSymbolAddress((void**)&pWTh,  g_WTh);
    cudaGetSymbolAddress((void**)&pWuTh, g_WuTh);

    dim3 tb(32, 8);
    k_packx<<<MMALL * DD / 256, 256>>>(x);
    k_packw<<<dim3(NNQKV / 32, DD / 32), tb>>>(Wq, pWTh,                  DD, NNQKV);
    k_packw<<<dim3(NNQKV / 32, DD / 32), tb>>>(Wk, pWTh + NNQKV * DD,     DD, NNQKV);
    k_packw<<<dim3(NNQKV / 32, DD / 32), tb>>>(Wv, pWTh + 2 * NNQKV * DD, DD, NNQKV);
    k_packw<<<dim3(DD / 32, NNQKV / 32), tb>>>(Wu, pWuTh,                 NNQKV, DD);

    k_qkv <<<dim3(NNQKV / 128, MMALL / 128, 3), 256, SM1>>>();
    k_attn<<<dim3(TT / 128, BH), 256, SM_ATT>>>();
    k_out <<<dim3(DD / 128, MMALL / 128, 1), 256, SM1>>>(bu, out);
}

// round 16
// speedup vs baseline: 5.5047x; 1.0183x over previous
#include <cuda_runtime.h>
#include <cuda_fp16.h>
#include <cstdint>

#define BB   8
#define TT   1024
#define DD   256
#define HH   8
#define BH   (BB*HH)      // 64
#define MMALL (BB*TT)     // 8192
#define NNQKV (HH*DD)     // 2048

// ---------------------------------------------------------------------------
// Device scratch (no allocations allowed). 16B-aligned for half2/cp.async.
// ---------------------------------------------------------------------------
__device__ __align__(16) __half g_Xh [MMALL*DD];
__device__ __align__(16) __half g_WTh[3*NNQKV*DD];      // [n=2048][k=256] per z
__device__ __align__(16) __half g_WuTh[DD*NNQKV];       // [n=256][k=2048]
__device__ __align__(16) __half g_Qh [BH*TT*DD];        // [bh][t][d], x(0.25*log2e)
__device__ __align__(16) __half g_Kh [BH*TT*DD];        // [bh][t][d], x0.25
__device__ __align__(16) __half g_VT [BH*DD*TT];        // [bh][d][t]
__device__ __align__(16) __half g_Oh [MMALL*NNQKV];     // [b*t][h*d]
__device__ __align__(16) float  g_Pa [MMALL*DD];        // out-proj partial k-slice 0
__device__ __align__(16) float  g_Pb [MMALL*DD];        // out-proj partial k-slice 1

// ---------------------------------------------------------------------------
// PTX helpers (sm_80-era instructions only; valid at sm_103 base target)
// ---------------------------------------------------------------------------
__device__ __forceinline__ uint32_t smem_u32(const void* p){
    uint32_t a;
    asm("{ .reg .u64 t; cvta.to.shared.u64 t, %1; cvt.u32.u64 %0, t; }" : "=r"(a) : "l"(p));
    return a;
}
__device__ __forceinline__ void cp_async16(uint32_t dst, const __half* src){
    uint64_t g; asm("cvta.to.global.u64 %0, %1;" : "=l"(g) : "l"(src));
    asm volatile("cp.async.ca.shared.global [%0], [%1], 16;" :: "r"(dst), "l"(g));
}
__device__ __forceinline__ void cp_commit(){ asm volatile("cp.async.commit_group;" ::: "memory"); }
template<int N> __device__ __forceinline__ void cp_wait(){
    asm volatile("cp.async.wait_group %0;" :: "n"(N) : "memory");
}
__device__ __forceinline__ void ldsm4(uint32_t r[4], uint32_t addr){
    asm volatile("ldmatrix.sync.aligned.m8n8.x4.shared.b16 {%0,%1,%2,%3}, [%4];"
        : "=r"(r[0]), "=r"(r[1]), "=r"(r[2]), "=r"(r[3]) : "r"(addr));
}
__device__ __forceinline__ void mma16816(float c[4], const uint32_t a[4],
                                         uint32_t b0, uint32_t b1){
    asm volatile("mma.sync.aligned.m16n8k16.row.col.f32.f16.f16.f32 "
        "{%0,%1,%2,%3},{%4,%5,%6,%7},{%8,%9},{%0,%1,%2,%3};"
        : "+f"(c[0]), "+f"(c[1]), "+f"(c[2]), "+f"(c[3])
        : "r"(a[0]), "r"(a[1]), "r"(a[2]), "r"(a[3]), "r"(b0), "r"(b1));
}
__device__ __forceinline__ float ex2f(float x){
    float y; asm("ex2.approx.f32 %0, %1;" : "=f"(y) : "f"(x)); return y;
}

// ---------------------------------------------------------------------------
// GEMM core (projections): C[128,128] = A[128xK] @ B[128xK]^T, both K-major.
// 8 warps (2x4 grid of 64x32 warp tiles). BK=64, 2-stage cp.async pipeline.
// SMEM row stride 144B (odd multiple of 16) -> conflict-free, 2 CTAs/SM.
// ---------------------------------------------------------------------------
#define ROWB     144
#define TILE_B   (128*ROWB)         // 18432
#define SM_G     (2*2*TILE_B)       // 73728

template<class Epi>
__device__ __forceinline__ void gemm_core(
    const __half* __restrict__ A, int lda,
    const __half* __restrict__ B, int ldb,
    int m0, int n0, int K, Epi&& epi)
{
    extern __shared__ __half smbuf[];
    const uint32_t smb = smem_u32(smbuf);
    const int tid  = threadIdx.x;
    const int lane = tid & 31, w = tid >> 5;

    const int lrow = lane + 32 * (w & 3);
    const int lch0 = (w >> 2) * 4;          // 4 consecutive 16B chunks

    float c[4][4][4];
#pragma unroll
    for (int i = 0; i < 4; i++)
#pragma unroll
        for (int j = 0; j < 4; j++)
#pragma unroll
            for (int q = 0; q < 4; q++) c[i][j][q] = 0.f;

    auto ldst = [&](int t, const __half* src, int ld, int rowbase, int k0, int buf){
        const __half* s = src + (size_t)(rowbase + lrow) * ld + k0 + lch0 * 8;
        uint32_t d = smb + (buf * 2 + t) * TILE_B + lrow * ROWB + lch0 * 16;
        cp_async16(d,      s);
        cp_async16(d + 16, s + 8);
        cp_async16(d + 32, s + 16);
        cp_async16(d + 48, s + 24);
    };
    auto load_stage = [&](int k0, int buf){
        ldst(0, A, lda, m0, k0, buf);
        ldst(1, B, ldb, n0, k0, buf);
        cp_commit();
    };

    const int wm = w & 1, wn = w >> 1;
    const uint32_t lA = (uint32_t)(lane & 15) * ROWB + (uint32_t)(lane >> 4) * 16;
    const uint32_t aOff = (uint32_t)(wm * 64) * ROWB + lA;
    const uint32_t bOff = (uint32_t)(wn * 32) * ROWB + lA;

    load_stage(0, 0);
    const int NST = K >> 6;
    for (int s = 0; s < NST; s++) {
        if (s + 1 < NST) { load_stage((s + 1) << 6, (s + 1) & 1); cp_wait<1>(); }
        else             { cp_wait<0>(); }
        __syncthreads();

        const int buf = s & 1;
        const uint32_t aB = smb + (buf * 2 + 0) * TILE_B + aOff;
        const uint32_t bB = smb + (buf * 2 + 1) * TILE_B + bOff;

#pragma unroll
        for (int k16 = 0; k16 < 4; k16++) {
            const uint32_t kb = k16 * 32;
            uint32_t a[4][4];
#pragma unroll
            for (int mi = 0; mi < 4; mi++) ldsm4(a[mi], aB + mi * (16*ROWB) + kb);
            uint32_t b[2][4];
#pragma unroll
            for (int nj = 0; nj < 2; nj++) ldsm4(b[nj], bB + nj * (16*ROWB) + kb);
#pragma unroll
            for (int mi = 0; mi < 4; mi++)
#pragma unroll
                for (int ni = 0; ni < 4; ni++) {
                    const int nj = ni >> 1, sel = ni & 1;
                    mma16816(c[mi][ni], a[mi], b[nj][sel], b[nj][sel + 2]);
                }
        }
        __syncthreads();
    }

#pragma unroll
    for (int mi = 0; mi < 4; mi++)
#pragma unroll
        for (int h8 = 0; h8 < 2; h8++) {
            const int row = m0 + wm * 64 + mi * 16 + (lane >> 2) + h8 * 8;
#pragma unroll
            for (int ni = 0; ni < 4; ni++) {
                const int col = n0 + wn * 32 + ni * 8 + (lane & 3) * 2;
                epi(row, col, make_float2(c[mi][ni][h8 * 2], c[mi][ni][h8 * 2 + 1]));
            }
        }
}

// ---------------------------------------------------------------------------
// Unified pack kernel. grid (64, 8, 5), block (32, 8).
//  z=0 : X fp32 -> fp16 streaming convert (grid-stride)
//  z=1..3 : Wq/Wk/Wv [256][2048] -> transpose fp16 [2048][256]
//  z=4 : Wu [2048][256] -> transpose fp16 [256][2048]
// ---------------------------------------------------------------------------
__global__ void k_pack(const float* __restrict__ x,  const float* __restrict__ Wq,
                       const float* __restrict__ Wk, const float* __restrict__ Wv,
                       const float* __restrict__ Wu){
    const int z = blockIdx.z;
    const int tx = threadIdx.x, ty = threadIdx.y;
    if (z == 0) {
        int t = (blockIdx.y * 64 + blockIdx.x) * 256 + ty * 32 + tx;
        for (int i = t; i < MMALL * DD; i += 64 * 8 * 256)
            g_Xh[i] = __float2half_rn(x[i]);
        return;
    }
    __shared__ float tbuf[32][33];
    if (z <= 3) {   // W [256][2048] -> [2048][256]
        const float* W = (z == 1) ? Wq : (z == 2) ? Wk : Wv;
        __half* out = g_WTh + (size_t)(z - 1) * NNQKV * DD;
        int c0 = blockIdx.x * 32, r0 = blockIdx.y * 32;
#pragma unroll
        for (int i = 0; i < 32; i += 8) tbuf[ty + i][tx] = W[(size_t)(r0 + ty + i) * NNQKV + c0 + tx];
        __syncthreads();
#pragma unroll
        for (int i = 0; i < 32; i += 8)
            out[(size_t)(c0 + ty + i) * DD + r0 + tx] = __float2half_rn(tbuf[tx][ty + i]);
    } else {        // Wu [2048][256] -> [256][2048]
        int r0 = blockIdx.x * 32, c0 = blockIdx.y * 32;
#pragma unroll
        for (int i = 0; i < 32; i += 8) tbuf[ty + i][tx] = Wu[(size_t)(r0 + ty + i) * DD + c0 + tx];
        __syncthreads();
#pragma unroll
        for (int i = 0; i < 32; i += 8)
            g_WuTh[(size_t)(c0 + ty + i) * NNQKV + r0 + tx] = __float2half_rn(tbuf[tx][ty + i]);
    }
}

// ---------------------------------------------------------------------------
// Projection kernels
// ---------------------------------------------------------------------------
#define QSCALE (0.25f * 1.44269504f)    // fold log2(e) into Q so exp == ex2

__global__ __launch_bounds__(256, 2) void k_qkv(){
    const int z = blockIdx.z;
    const int m0 = blockIdx.y * 128, n0 = blockIdx.x * 128;
    const __half* Bh_ = g_WTh + (size_t)z * NNQKV * DD;
    gemm_core(g_Xh, DD, Bh_, DD, m0, n0, DD,
        [&](int row, int col, float2 v){
            int b = row >> 10, t = row & 1023, h = col >> 8, d = col & 255;
            if (z == 2) {
                // write V transposed: [bh][d][t]
                __half* dst = g_VT + ((size_t)(b * HH + h) * DD + d) * TT + t;
                dst[0]  = __float2half_rn(v.x);
                dst[TT] = __float2half_rn(v.y);
            } else {
                size_t o = ((size_t)(b * HH + h) * TT + t) * DD + d;
                const float sc = (z == 0) ? QSCALE : 0.25f;
                __half* Hh = (z == 0) ? g_Qh : g_Kh;
                *reinterpret_cast<__half2*>(&Hh[o]) =
                    __halves2half2(__float2half_rn(v.x * sc), __float2half_rn(v.y * sc));
            }
        });
}

// out-projection, split-K=2: kz selects K slice [kz*1024, kz*1024+1024)
__global__ __launch_bounds__(256, 2) void k_out(){
    const int m0 = blockIdx.y * 128, n0 = blockIdx.x * 128;
    const int kz = blockIdx.z;
    float* dst = kz ? g_Pb : g_Pa;
    gemm_core(g_Oh + kz * 1024, NNQKV, g_WuTh + kz * 1024, NNQKV, m0, n0, 1024,
        [&](int row, int col, float2 v){
            *reinterpret_cast<float2*>(dst + (size_t)row * DD + col) = v;
        });
}

__global__ void k_red(const float* __restrict__ bu, float* __restrict__ out){
    int i4 = blockIdx.x * 256 + threadIdx.x;
    int base = i4 * 4;
    float4 a = *reinterpret_cast<const float4*>(g_Pa + base);
    float4 b = *reinterpret_cast<const float4*>(g_Pb + base);
    float4 bias = *reinterpret_cast<const float4*>(bu + (base & (DD - 1)));
    float4 o;
    o.x = a.x + b.x + bias.x; o.y = a.y + b.y + bias.y;
    o.z = a.z + b.z + bias.z; o.w = a.w + b.w + bias.w;
    *reinterpret_cast<float4*>(out + base) = o;
}

// ---------------------------------------------------------------------------
// Fused flash attention: per CTA = (bh, 128 q-rows), warp = 16 rows x full s.
// Loop over 16 key-tiles of 64: S = Q@K^T (mma), ex2 in regs, P-frag reuse
// (C-frag == A-frag layout), O += P@V^T, row sums in-warp. Normalize at end.
// SMEM: Q 66K + K 2x33K + VT 2x36K = 204 KB.
// ---------------------------------------------------------------------------
#define QSTR 528            // 256 halves + 16B pad (odd multiple of 16)
#define VSTR 144            // 64 halves + 16B pad
#define KS_OFF   (128*QSTR)             // 67584
#define VS_OFF   (KS_OFF + 2*64*QSTR)   // 135168
#define SM_ATT   (VS_OFF + 2*256*VSTR)  // 208896

__global__ __launch_bounds__(256) void k_attn(){
    extern __shared__ __half smbuf[];
    const uint32_t smb = smem_u32(smbuf);
    const int bh = blockIdx.y;
    const int q0 = blockIdx.x * 128;
    const int tid = threadIdx.x, lane = tid & 31, w = tid >> 5;

    const __half* Qg = g_Qh + (size_t)bh * TT * DD + (size_t)q0 * DD;
    const __half* Kg = g_Kh + (size_t)bh * TT * DD;
    const __half* Vg = g_VT + (size_t)bh * DD * TT;

    // Q load: 128 rows x 512B
#pragma unroll
    for (int p = 0; p < 16; p++) {
        int i = p * 256 + tid, r = i >> 5, ch = i & 31;
        cp_async16(smb + r * QSTR + ch * 16, Qg + r * DD + ch * 8);
    }
    auto loadKV = [&](int it, int buf){
        const __half* Kt = Kg + (size_t)it * 64 * DD;
#pragma unroll
        for (int p = 0; p < 8; p++) {
            int i = p * 256 + tid, r = i >> 5, ch = i & 31;
            cp_async16(smb + KS_OFF + buf * (64*QSTR) + r * QSTR + ch * 16,
                       Kt + r * DD + ch * 8);
        }
#pragma unroll
        for (int p = 0; p < 8; p++) {
            int i = p * 256 + tid, r = i >> 3, ch = i & 7;
            cp_async16(smb + VS_OFF + buf * (256*VSTR) + r * VSTR + ch * 16,
                       Vg + (size_t)r * TT + it * 64 + ch * 8);
        }
        cp_commit();
    };
    loadKV(0, 0);

    float o[32][4];
#pragma unroll
    for (int j = 0; j < 32; j++)
#pragma unroll
        for (int q = 0; q < 4; q++) o[j][q] = 0.f;
    float rs0 = 0.f, rs1 = 0.f;

    const uint32_t lA = (uint32_t)(lane & 15) * QSTR + (uint32_t)(lane >> 4) * 16;
    const uint32_t aB = smb + (uint32_t)(16 * w) * QSTR + lA;
    const uint32_t vL = (uint32_t)(lane & 15) * VSTR + (uint32_t)(lane >> 4) * 16;

    for (int it = 0; it < 16; it++) {
        cp_wait<0>();
        __syncthreads();
        if (it + 1 < 16) loadKV(it + 1, (it + 1) & 1);
        const int buf = it & 1;
        const uint32_t kB = smb + KS_OFF + buf * (64*QSTR) + lA;

        // --- S = Q @ K^T : 16 rows x 64 cols per warp ---
        float c[8][4];
#pragma unroll
        for (int j = 0; j < 8; j++)
#pragma unroll
            for (int q = 0; q < 4; q++) c[j][q] = 0.f;
#pragma unroll
        for (int ks = 0; ks < 16; ks++) {
            uint32_t a[4]; ldsm4(a, aB + ks * 32);
#pragma unroll
            for (int g = 0; g < 4; g++) {
                uint32_t b[4]; ldsm4(b, kB + g * (16*QSTR) + ks * 32);
                mma16816(c[2*g],     a, b[0], b[2]);
                mma16816(c[2*g + 1], a, b[1], b[3]);
            }
        }

        // --- ex2 -> P frags (C-frag == A-frag layout), row sums from rounded P ---
        uint32_t p[4][4];
#pragma unroll
        for (int j = 0; j < 8; j++)
#pragma unroll
            for (int q = 0; q < 4; q++) c[j][q] = ex2f(c[j][q]);
#pragma unroll
        for (int ks2 = 0; ks2 < 4; ks2++) {
            const int j0 = 2 * ks2, j1 = j0 + 1;
            __half2 h00 = __floats2half2_rn(c[j0][0], c[j0][1]);
            __half2 h01 = __floats2half2_rn(c[j0][2], c[j0][3]);
            __half2 h10 = __floats2half2_rn(c[j1][0], c[j1][1]);
            __half2 h11 = __floats2half2_rn(c[j1][2], c[j1][3]);
            p[ks2][0] = *reinterpret_cast<uint32_t*>(&h00);
            p[ks2][1] = *reinterpret_cast<uint32_t*>(&h01);
            p[ks2][2] = *reinterpret_cast<uint32_t*>(&h10);
            p[ks2][3] = *reinterpret_cast<uint32_t*>(&h11);
            float2 f;
            f = __half22float2(h00); rs0 += f.x + f.y;
            f = __half22float2(h10); rs0 += f.x + f.y;
            f = __half22float2(h01); rs1 += f.x + f.y;
            f = __half22float2(h11); rs1 += f.x + f.y;
        }

        // --- O += P @ V^T : contraction over s=64, n = d = 256 ---
        const uint32_t vB = smb + VS_OFF + buf * (256*VSTR) + vL;
#pragma unroll
        for (int ks2 = 0; ks2 < 4; ks2++) {
#pragma unroll
            for (int dg = 0; dg < 16; dg++) {
                uint32_t b[4]; ldsm4(b, vB + dg * (16*VSTR) + ks2 * 32);
                mma16816(o[2*dg],     p[ks2], b[0], b[2]);
                mma16816(o[2*dg + 1], p[ks2], b[1], b[3]);
            }
        }
    }

    // --- finalize ---
    rs0 += __shfl_xor_sync(0xffffffffu, rs0, 1);
    rs0 += __shfl_xor_sync(0xffffffffu, rs0, 2);
    rs1 += __shfl_xor_sync(0xffffffffu, rs1, 1);
    rs1 += __shfl_xor_sync(0xffffffffu, rs1, 2);
    const float inv0 = 1.0f / rs0, inv1 = 1.0f / rs1;

    const int b = bh >> 3, h = bh & 7;
    const int r0 = q0 + 16 * w + (lane >> 2), r1 = r0 + 8;
    __half* Oh0 = g_Oh + (size_t)(b * TT + r0) * NNQKV + h * DD;
    __half* Oh1 = g_Oh + (size_t)(b * TT + r1) * NNQKV + h * DD;
#pragma unroll
    for (int j = 0; j < 32; j++) {
        const int col = j * 8 + (lane & 3) * 2;
        *reinterpret_cast<__half2*>(Oh0 + col) =
            __floats2half2_rn(o[j][0] * inv0, o[j][1] * inv0);
        *reinterpret_cast<__half2*>(Oh1 + col) =
            __floats2half2_rn(o[j][2] * inv1, o[j][3] * inv1);
    }
}

// ---------------------------------------------------------------------------
extern "C" void kernel_launch(void* const* d_in, const int* in_sizes, int n_in,
                              void* d_out, int out_size)
{
    const float* x  = (const float*)d_in[0];
    const float* Wq = (const float*)d_in[1];
    const float* Wk = (const float*)d_in[2];
    const float* Wv = (const float*)d_in[3];
    const float* Wu = (const float*)d_in[4];
    const float* bu = (const float*)d_in[5];
    float* out = (float*)d_out;

    cudaFuncSetAttribute(k_qkv,  cudaFuncAttributeMaxDynamicSharedMemorySize, SM_G);
    cudaFuncSetAttribute(k_out,  cudaFuncAttributeMaxDynamicSharedMemorySize, SM_G);
    cudaFuncSetAttribute(k_attn, cudaFuncAttributeMaxDynamicSharedMemorySize, SM_ATT);

    k_pack<<<dim3(64, 8, 5), dim3(32, 8)>>>(x, Wq, Wk, Wv, Wu);
    k_qkv <<<dim3(NNQKV / 128, MMALL / 128, 3), 256, SM_G>>>();
    k_attn<<<dim3(TT / 128, BH), 256, SM_ATT>>>();
    k_out <<<dim3(DD / 128, MMALL / 128, 2), 256, SM_G>>>();
    k_red <<<MMALL * DD / 4 / 256, 256>>>(bu, out);
}

// round 17
// speedup vs baseline: 5.8326x; 1.0596x over previous
#include <cuda_runtime.h>
#include <cuda_fp16.h>
#include <cstdint>

#define BB   8
#define TT   1024
#define DD   256
#define HH   8
#define BH   (BB*HH)      // 64
#define MMALL (BB*TT)     // 8192
#define NNQKV (HH*DD)     // 2048

// ---------------------------------------------------------------------------
// Device scratch (no allocations allowed). 16B-aligned for half2/cp.async.
// ---------------------------------------------------------------------------
__device__ __align__(16) __half g_Xh [MMALL*DD];
__device__ __align__(16) __half g_WTh[3*NNQKV*DD];      // [n=2048][k=256] per z
__device__ __align__(16) __half g_WuTh[DD*NNQKV];       // [n=256][k=2048]
__device__ __align__(16) __half g_Qh [BH*TT*DD];        // [bh][t][d], x(0.25*log2e)
__device__ __align__(16) __half g_Kh [BH*TT*DD];        // [bh][t][d], x0.25
__device__ __align__(16) __half g_VT [BH*DD*TT];        // [bh][d][t]
__device__ __align__(16) __half g_Oh [MMALL*NNQKV];     // [b*t][h*d]
__device__ __align__(16) float  g_Pa [MMALL*DD];        // out-proj partial k-slice 0
__device__ __align__(16) float  g_Pb [MMALL*DD];        // out-proj partial k-slice 1

// ---------------------------------------------------------------------------
// PTX helpers (sm_80-era instructions only; valid at sm_103 base target)
// ---------------------------------------------------------------------------
__device__ __forceinline__ uint32_t smem_u32(const void* p){
    uint32_t a;
    asm("{ .reg .u64 t; cvta.to.shared.u64 t, %1; cvt.u32.u64 %0, t; }" : "=r"(a) : "l"(p));
    return a;
}
__device__ __forceinline__ void cp_async16(uint32_t dst, const __half* src){
    uint64_t g; asm("cvta.to.global.u64 %0, %1;" : "=l"(g) : "l"(src));
    asm volatile("cp.async.ca.shared.global [%0], [%1], 16;" :: "r"(dst), "l"(g));
}
__device__ __forceinline__ void cp_commit(){ asm volatile("cp.async.commit_group;" ::: "memory"); }
template<int N> __device__ __forceinline__ void cp_wait(){
    asm volatile("cp.async.wait_group %0;" :: "n"(N) : "memory");
}
__device__ __forceinline__ void ldsm4(uint32_t r[4], uint32_t addr){
    asm volatile("ldmatrix.sync.aligned.m8n8.x4.shared.b16 {%0,%1,%2,%3}, [%4];"
        : "=r"(r[0]), "=r"(r[1]), "=r"(r[2]), "=r"(r[3]) : "r"(addr));
}
__device__ __forceinline__ void mma16816(float c[4], const uint32_t a[4],
                                         uint32_t b0, uint32_t b1){
    asm volatile("mma.sync.aligned.m16n8k16.row.col.f32.f16.f16.f32 "
        "{%0,%1,%2,%3},{%4,%5,%6,%7},{%8,%9},{%0,%1,%2,%3};"
        : "+f"(c[0]), "+f"(c[1]), "+f"(c[2]), "+f"(c[3])
        : "r"(a[0]), "r"(a[1]), "r"(a[2]), "r"(a[3]), "r"(b0), "r"(b1));
}
__device__ __forceinline__ float ex2f(float x){
    float y; asm("ex2.approx.f32 %0, %1;" : "=f"(y) : "f"(x)); return y;
}

// ---------------------------------------------------------------------------
// GEMM core (projections): C[128,256] = A[128xK] @ B[256xK]^T, both K-major.
// 8 warps in 2x4 grid, warp tile 64x64 -> 4.0 MMA per ldmatrix (LDS-bound fix).
// BK=64, 2-stage cp.async pipeline. Row stride 144B -> conflict-free ldsm.
// SMEM 110.6KB, ~180 regs -> 1 CTA/SM.
// ---------------------------------------------------------------------------
#define ROWB     144
#define A_TILE   (128*ROWB)          // 18432
#define B_TILE   (256*ROWB)          // 36864
#define ST_B     (A_TILE + B_TILE)   // 55296
#define SM_G     (2*ST_B)            // 110592

template<class Epi>
__device__ __forceinline__ void gemm_core(
    const __half* __restrict__ A, int lda,
    const __half* __restrict__ B, int ldb,
    int m0, int n0, int K, Epi&& epi)
{
    extern __shared__ __half smbuf[];
    const uint32_t smb = smem_u32(smbuf);
    const int tid  = threadIdx.x;
    const int lane = tid & 31, w = tid >> 5;

    const int lrow = lane + 32 * (w & 3);   // 0..127
    const int lch0 = (w >> 2) * 4;          // chunk group {0..3} or {4..7} of 8

    float c[4][8][4];
#pragma unroll
    for (int i = 0; i < 4; i++)
#pragma unroll
        for (int j = 0; j < 8; j++)
#pragma unroll
            for (int q = 0; q < 4; q++) c[i][j][q] = 0.f;

    auto load_stage = [&](int k0, int buf){
        const __half* sA = A + (size_t)(m0 + lrow) * lda + k0 + lch0 * 8;
        uint32_t dA = smb + buf * ST_B + lrow * ROWB + lch0 * 16;
        cp_async16(dA,      sA);
        cp_async16(dA + 16, sA + 8);
        cp_async16(dA + 32, sA + 16);
        cp_async16(dA + 48, sA + 24);
#pragma unroll
        for (int rb = 0; rb < 2; rb++) {
            const __half* sB = B + (size_t)(n0 + rb * 128 + lrow) * ldb + k0 + lch0 * 8;
            uint32_t dB = smb + buf * ST_B + A_TILE + (rb * 128 + lrow) * ROWB + lch0 * 16;
            cp_async16(dB,      sB);
            cp_async16(dB + 16, sB + 8);
            cp_async16(dB + 32, sB + 16);
            cp_async16(dB + 48, sB + 24);
        }
        cp_commit();
    };

    const int wm = w & 1, wn = w >> 1;      // 2 x 4 warp grid
    const uint32_t lA = (uint32_t)(lane & 15) * ROWB + (uint32_t)(lane >> 4) * 16;
    const uint32_t aOff = (uint32_t)(wm * 64) * ROWB + lA;
    const uint32_t bOff = A_TILE + (uint32_t)(wn * 64) * ROWB + lA;

    load_stage(0, 0);
    const int NST = K >> 6;
    for (int s = 0; s < NST; s++) {
        if (s + 1 < NST) { load_stage((s + 1) << 6, (s + 1) & 1); cp_wait<1>(); }
        else             { cp_wait<0>(); }
        __syncthreads();

        const int buf = s & 1;
        const uint32_t aB = smb + buf * ST_B + aOff;
        const uint32_t bB = smb + buf * ST_B + bOff;

#pragma unroll
        for (int k16 = 0; k16 < 4; k16++) {
            const uint32_t kb = k16 * 32;
            uint32_t a[4][4];
#pragma unroll
            for (int mi = 0; mi < 4; mi++) ldsm4(a[mi], aB + mi * (16*ROWB) + kb);
            uint32_t b[4][4];
#pragma unroll
            for (int nj = 0; nj < 4; nj++) ldsm4(b[nj], bB + nj * (16*ROWB) + kb);
#pragma unroll
            for (int mi = 0; mi < 4; mi++)
#pragma unroll
                for (int ni = 0; ni < 8; ni++) {
                    const int nj = ni >> 1, sel = ni & 1;
                    mma16816(c[mi][ni], a[mi], b[nj][sel], b[nj][sel + 2]);
                }
        }
        __syncthreads();
    }

#pragma unroll
    for (int mi = 0; mi < 4; mi++)
#pragma unroll
        for (int h8 = 0; h8 < 2; h8++) {
            const int row = m0 + wm * 64 + mi * 16 + (lane >> 2) + h8 * 8;
#pragma unroll
            for (int ni = 0; ni < 8; ni++) {
                const int col = n0 + wn * 64 + ni * 8 + (lane & 3) * 2;
                epi(row, col, make_float2(c[mi][ni][h8 * 2], c[mi][ni][h8 * 2 + 1]));
            }
        }
}

// ---------------------------------------------------------------------------
// Unified pack kernel. grid (64, 8, 5), block (32, 8).
//  z=0 : X fp32 -> fp16 streaming convert (grid-stride)
//  z=1..3 : Wq/Wk/Wv [256][2048] -> transpose fp16 [2048][256]
//  z=4 : Wu [2048][256] -> transpose fp16 [256][2048]
// ---------------------------------------------------------------------------
__global__ void k_pack(const float* __restrict__ x,  const float* __restrict__ Wq,
                       const float* __restrict__ Wk, const float* __restrict__ Wv,
                       const float* __restrict__ Wu){
    const int z = blockIdx.z;
    const int tx = threadIdx.x, ty = threadIdx.y;
    if (z == 0) {
        int t = (blockIdx.y * 64 + blockIdx.x) * 256 + ty * 32 + tx;
        for (int i = t; i < MMALL * DD; i += 64 * 8 * 256)
            g_Xh[i] = __float2half_rn(x[i]);
        return;
    }
    __shared__ float tbuf[32][33];
    if (z <= 3) {   // W [256][2048] -> [2048][256]
        const float* W = (z == 1) ? Wq : (z == 2) ? Wk : Wv;
        __half* out = g_WTh + (size_t)(z - 1) * NNQKV * DD;
        int c0 = blockIdx.x * 32, r0 = blockIdx.y * 32;
#pragma unroll
        for (int i = 0; i < 32; i += 8) tbuf[ty + i][tx] = W[(size_t)(r0 + ty + i) * NNQKV + c0 + tx];
        __syncthreads();
#pragma unroll
        for (int i = 0; i < 32; i += 8)
            out[(size_t)(c0 + ty + i) * DD + r0 + tx] = __float2half_rn(tbuf[tx][ty + i]);
    } else {        // Wu [2048][256] -> [256][2048]
        int r0 = blockIdx.x * 32, c0 = blockIdx.y * 32;
#pragma unroll
        for (int i = 0; i < 32; i += 8) tbuf[ty + i][tx] = Wu[(size_t)(r0 + ty + i) * DD + c0 + tx];
        __syncthreads();
#pragma unroll
        for (int i = 0; i < 32; i += 8)
            g_WuTh[(size_t)(c0 + ty + i) * NNQKV + r0 + tx] = __float2half_rn(tbuf[tx][ty + i]);
    }
}

// ---------------------------------------------------------------------------
// Projection kernels
// ---------------------------------------------------------------------------
#define QSCALE (0.25f * 1.44269504f)    // fold log2(e) into Q so exp == ex2

__global__ __launch_bounds__(256, 1) void k_qkv(){
    const int z = blockIdx.z;
    const int m0 = blockIdx.y * 128, n0 = blockIdx.x * 256;
    const __half* Bh_ = g_WTh + (size_t)z * NNQKV * DD;
    gemm_core(g_Xh, DD, Bh_, DD, m0, n0, DD,
        [&](int row, int col, float2 v){
            int b = row >> 10, t = row & 1023, h = col >> 8, d = col & 255;
            if (z == 2) {
                // write V transposed: [bh][d][t]
                __half* dst = g_VT + ((size_t)(b * HH + h) * DD + d) * TT + t;
                dst[0]  = __float2half_rn(v.x);
                dst[TT] = __float2half_rn(v.y);
            } else {
                size_t o = ((size_t)(b * HH + h) * TT + t) * DD + d;
                const float sc = (z == 0) ? QSCALE : 0.25f;
                __half* Hh = (z == 0) ? g_Qh : g_Kh;
                *reinterpret_cast<__half2*>(&Hh[o]) =
                    __halves2half2(__float2half_rn(v.x * sc), __float2half_rn(v.y * sc));
            }
        });
}

// out-projection, split-K=2: kz selects K slice [kz*1024, kz*1024+1024)
__global__ __launch_bounds__(256, 1) void k_out(){
    const int m0 = blockIdx.y * 128, n0 = 0;
    const int kz = blockIdx.z;
    float* dst = kz ? g_Pb : g_Pa;
    gemm_core(g_Oh + kz * 1024, NNQKV, g_WuTh + kz * 1024, NNQKV, m0, n0, 1024,
        [&](int row, int col, float2 v){
            *reinterpret_cast<float2*>(dst + (size_t)row * DD + col) = v;
        });
}

__global__ void k_red(const float* __restrict__ bu, float* __restrict__ out){
    int i4 = blockIdx.x * 256 + threadIdx.x;
    int base = i4 * 4;
    float4 a = *reinterpret_cast<const float4*>(g_Pa + base);
    float4 b = *reinterpret_cast<const float4*>(g_Pb + base);
    float4 bias = *reinterpret_cast<const float4*>(bu + (base & (DD - 1)));
    float4 o;
    o.x = a.x + b.x + bias.x; o.y = a.y + b.y + bias.y;
    o.z = a.z + b.z + bias.z; o.w = a.w + b.w + bias.w;
    *reinterpret_cast<float4*>(out + base) = o;
}

// ---------------------------------------------------------------------------
// Fused flash attention: per CTA = (bh, 128 q-rows), warp = 16 rows x full s.
// Loop over 16 key-tiles of 64: S = Q@K^T (mma), ex2 in regs, P-frag reuse
// (C-frag == A-frag layout), O += P@V^T, row sums in-warp. Normalize at end.
// SMEM: Q 66K + K 2x33K + VT 2x36K = 204 KB.
// ---------------------------------------------------------------------------
#define QSTR 528            // 256 halves + 16B pad (odd multiple of 16)
#define VSTR 144            // 64 halves + 16B pad
#define KS_OFF   (128*QSTR)             // 67584
#define VS_OFF   (KS_OFF + 2*64*QSTR)   // 135168
#define SM_ATT   (VS_OFF + 2*256*VSTR)  // 208896

__global__ __launch_bounds__(256) void k_attn(){
    extern __shared__ __half smbuf[];
    const uint32_t smb = smem_u32(smbuf);
    const int bh = blockIdx.y;
    const int q0 = blockIdx.x * 128;
    const int tid = threadIdx.x, lane = tid & 31, w = tid >> 5;

    const __half* Qg = g_Qh + (size_t)bh * TT * DD + (size_t)q0 * DD;
    const __half* Kg = g_Kh + (size_t)bh * TT * DD;
    const __half* Vg = g_VT + (size_t)bh * DD * TT;

    // Q load: 128 rows x 512B
#pragma unroll
    for (int p = 0; p < 16; p++) {
        int i = p * 256 + tid, r = i >> 5, ch = i & 31;
        cp_async16(smb + r * QSTR + ch * 16, Qg + r * DD + ch * 8);
    }
    auto loadKV = [&](int it, int buf){
        const __half* Kt = Kg + (size_t)it * 64 * DD;
#pragma unroll
        for (int p = 0; p < 8; p++) {
            int i = p * 256 + tid, r = i >> 5, ch = i & 31;
            cp_async16(smb + KS_OFF + buf * (64*QSTR) + r * QSTR + ch * 16,
                       Kt + r * DD + ch * 8);
        }
#pragma unroll
        for (int p = 0; p < 8; p++) {
            int i = p * 256 + tid, r = i >> 3, ch = i & 7;
            cp_async16(smb + VS_OFF + buf * (256*VSTR) + r * VSTR + ch * 16,
                       Vg + (size_t)r * TT + it * 64 + ch * 8);
        }
        cp_commit();
    };
    loadKV(0, 0);

    float o[32][4];
#pragma unroll
    for (int j = 0; j < 32; j++)
#pragma unroll
        for (int q = 0; q < 4; q++) o[j][q] = 0.f;
    float rs0 = 0.f, rs1 = 0.f;

    const uint32_t lA = (uint32_t)(lane & 15) * QSTR + (uint32_t)(lane >> 4) * 16;
    const uint32_t aB = smb + (uint32_t)(16 * w) * QSTR + lA;
    const uint32_t vL = (uint32_t)(lane & 15) * VSTR + (uint32_t)(lane >> 4) * 16;

    for (int it = 0; it < 16; it++) {
        cp_wait<0>();
        __syncthreads();
        if (it + 1 < 16) loadKV(it + 1, (it + 1) & 1);
        const int buf = it & 1;
        const uint32_t kB = smb + KS_OFF + buf * (64*QSTR) + lA;

        // --- S = Q @ K^T : 16 rows x 64 cols per warp ---
        float c[8][4];
#pragma unroll
        for (int j = 0; j < 8; j++)
#pragma unroll
            for (int q = 0; q < 4; q++) c[j][q] = 0.f;
#pragma unroll
        for (int ks = 0; ks < 16; ks++) {
            uint32_t a[4]; ldsm4(a, aB + ks * 32);
#pragma unroll
            for (int g = 0; g < 4; g++) {
                uint32_t b[4]; ldsm4(b, kB + g * (16*QSTR) + ks * 32);
                mma16816(c[2*g],     a, b[0], b[2]);
                mma16816(c[2*g + 1], a, b[1], b[3]);
            }
        }

        // --- ex2 -> P frags (C-frag == A-frag layout), row sums from rounded P ---
        uint32_t p[4][4];
#pragma unroll
        for (int j = 0; j < 8; j++)
#pragma unroll
            for (int q = 0; q < 4; q++) c[j][q] = ex2f(c[j][q]);
#pragma unroll
        for (int ks2 = 0; ks2 < 4; ks2++) {
            const int j0 = 2 * ks2, j1 = j0 + 1;
            __half2 h00 = __floats2half2_rn(c[j0][0], c[j0][1]);
            __half2 h01 = __floats2half2_rn(c[j0][2], c[j0][3]);
            __half2 h10 = __floats2half2_rn(c[j1][0], c[j1][1]);
            __half2 h11 = __floats2half2_rn(c[j1][2], c[j1][3]);
            p[ks2][0] = *reinterpret_cast<uint32_t*>(&h00);
            p[ks2][1] = *reinterpret_cast<uint32_t*>(&h01);
            p[ks2][2] = *reinterpret_cast<uint32_t*>(&h10);
            p[ks2][3] = *reinterpret_cast<uint32_t*>(&h11);
            float2 f;
            f = __half22float2(h00); rs0 += f.x + f.y;
            f = __half22float2(h10); rs0 += f.x + f.y;
            f = __half22float2(h01); rs1 += f.x + f.y;
            f = __half22float2(h11); rs1 += f.x + f.y;
        }

        // --- O += P @ V^T : contraction over s=64, n = d = 256 ---
        const uint32_t vB = smb + VS_OFF + buf * (256*VSTR) + vL;
#pragma unroll
        for (int ks2 = 0; ks2 < 4; ks2++) {
#pragma unroll
            for (int dg = 0; dg < 16; dg++) {
                uint32_t b[4]; ldsm4(b, vB + dg * (16*VSTR) + ks2 * 32);
                mma16816(o[2*dg],     p[ks2], b[0], b[2]);
                mma16816(o[2*dg + 1], p[ks2], b[1], b[3]);
            }
        }
    }

    // --- finalize ---
    rs0 += __shfl_xor_sync(0xffffffffu, rs0, 1);
    rs0 += __shfl_xor_sync(0xffffffffu, rs0, 2);
    rs1 += __shfl_xor_sync(0xffffffffu, rs1, 1);
    rs1 += __shfl_xor_sync(0xffffffffu, rs1, 2);
    const float inv0 = 1.0f / rs0, inv1 = 1.0f / rs1;

    const int b = bh >> 3, h = bh & 7;
    const int r0 = q0 + 16 * w + (lane >> 2), r1 = r0 + 8;
    __half* Oh0 = g_Oh + (size_t)(b * TT + r0) * NNQKV + h * DD;
    __half* Oh1 = g_Oh + (size_t)(b * TT + r1) * NNQKV + h * DD;
#pragma unroll
    for (int j = 0; j < 32; j++) {
        const int col = j * 8 + (lane & 3) * 2;
        *reinterpret_cast<__half2*>(Oh0 + col) =
            __floats2half2_rn(o[j][0] * inv0, o[j][1] * inv0);
        *reinterpret_cast<__half2*>(Oh1 + col) =
            __floats2half2_rn(o[j][2] * inv1, o[j][3] * inv1);
    }
}

// ---------------------------------------------------------------------------
extern "C" void kernel_launch(void* const* d_in, const int* in_sizes, int n_in,
                              void* d_out, int out_size)
{
    const float* x  = (const float*)d_in[0];
    const float* Wq = (const float*)d_in[1];
    const float* Wk = (const float*)d_in[2];
    const float* Wv = (const float*)d_in[3];
    const float* Wu = (const float*)d_in[4];
    const float* bu = (const float*)d_in[5];
    float* out = (float*)d_out;

    cudaFuncSetAttribute(k_qkv,  cudaFuncAttributeMaxDynamicSharedMemorySize, SM_G);
    cudaFuncSetAttribute(k_out,  cudaFuncAttributeMaxDynamicSharedMemorySize, SM_G);
    cudaFuncSetAttribute(k_attn, cudaFuncAttributeMaxDynamicSharedMemorySize, SM_ATT);

    k_pack<<<dim3(64, 8, 5), dim3(32, 8)>>>(x, Wq, Wk, Wv, Wu);
    k_qkv <<<dim3(NNQKV / 256, MMALL / 128, 3), 256, SM_G>>>();
    k_attn<<<dim3(TT / 128, BH), 256, SM_ATT>>>();
    k_out <<<dim3(1, MMALL / 128, 2), 256, SM_G>>>();
    k_red <<<MMALL * DD / 4 / 256, 256>>>(bu, out);
}